// round 1
// baseline (speedup 1.0000x reference)
#include <cuda_runtime.h>
#include <math.h>

#define NN 50000
#define EE 800000
#define XD 192

// ---------------- scratch (static device allocations) ----------------
static __device__ float g_xcomb[NN * 256];          // [N,256] x_comb
static __device__ float g_nuv[NN * 2];              // normalized uv
static __device__ float g_xlri[NN * 768];           // cols 0:256 x_l | 256:512 x_r | 512:768 identity
static __device__ float g_pre[NN * 256];            // pre-projection activations
static __device__ float g_logits[EE * 4];           // per-edge per-head logits
static __device__ float g_m[NN * 4];                // segment max
static __device__ float g_s[NN * 4];                // segment sumexp
static __device__ int   g_deg[NN];
static __device__ int   g_cur[NN];
static __device__ int   g_off[NN + 1];
static __device__ int   g_bkt[EE];                  // edge ids grouped by dst
static __device__ float g_W[768 * 256];             // concat(lin_l_w, lin_r_w, res_w)
static __device__ float g_B[768];                   // concat biases

__device__ __forceinline__ float wsum(float v) {
#pragma unroll
    for (int o = 16; o > 0; o >>= 1) v += __shfl_xor_sync(0xffffffffu, v, o);
    return v;
}

// ---------------- init ----------------
__global__ void k_init() {
    int t = blockIdx.x * blockDim.x + threadIdx.x;
    if (t < NN) { g_deg[t] = 0; g_cur[t] = 0; }
    if (t == 0) g_off[NN] = EE;
}

// ---------------- positional encoder + x_comb assembly (1 warp / node) -------
__global__ void k_node(const float* __restrict__ x, const float* __restrict__ kpts,
                       const float* __restrict__ pts3d,
                       const float* __restrict__ w1, const float* __restrict__ b1,
                       const float* __restrict__ g1, const float* __restrict__ bn1,
                       const float* __restrict__ w2, const float* __restrict__ b2,
                       const float* __restrict__ g2, const float* __restrict__ bn2) {
    int gw = (blockIdx.x * blockDim.x + threadIdx.x) >> 5;
    int lane = threadIdx.x & 31;
    int w = threadIdx.x >> 5;
    if (gw >= NN) return;
    int n = gw;

    float nu = kpts[n * 2]     * (1.0f / 1216.0f);
    float nv = kpts[n * 2 + 1] * (1.0f / 352.0f);
    float dep = pts3d[n * 3 + 2];
    dep = fminf(fmaxf(dep, 0.1f), 100.0f);

    // Linear(3,32)
    float h = nu * w1[lane * 3] + nv * w1[lane * 3 + 1] + dep * w1[lane * 3 + 2] + b1[lane];
    // LN(32) + SiLU
    float mu = wsum(h) * (1.0f / 32.0f);
    float d = h - mu;
    float var = wsum(d * d) * (1.0f / 32.0f);
    float y = d * rsqrtf(var + 1e-5f) * g1[lane] + bn1[lane];
    y = y / (1.0f + expf(-y));

    __shared__ float sh[8][32];
    sh[w][lane] = y;
    __syncwarp();

    // Linear(32,64): lane -> outputs lane, lane+32
    float o0 = b2[lane], o1 = b2[lane + 32];
#pragma unroll
    for (int j = 0; j < 32; j++) {
        float hv = sh[w][j];
        o0 += hv * w2[lane * 32 + j];
        o1 += hv * w2[(lane + 32) * 32 + j];
    }
    // LN(64)
    float mean = wsum(o0 + o1) * (1.0f / 64.0f);
    float d0 = o0 - mean, d1 = o1 - mean;
    float v2 = wsum(d0 * d0 + d1 * d1) * (1.0f / 64.0f);
    float r = rsqrtf(v2 + 1e-5f);
    float p0 = d0 * r * g2[lane] + bn2[lane];
    float p1 = d1 * r * g2[lane + 32] + bn2[lane + 32];

    float* row = &g_xcomb[n * 256];
    row[192 + lane] = p0;
    row[224 + lane] = p1;
#pragma unroll
    for (int i = 0; i < 6; i++) row[lane + i * 32] = x[n * XD + lane + i * 32];

    if (lane == 0) { g_nuv[2 * n] = nu; g_nuv[2 * n + 1] = nv; }
}

// ---------------- weight concat ----------------
__global__ void k_concat(const float* ll, const float* lr, const float* rw,
                         const float* lb, const float* rb, const float* resb) {
    int t = blockIdx.x * blockDim.x + threadIdx.x;
    if (t < 65536)        g_W[t] = ll[t];
    else if (t < 131072)  g_W[t] = lr[t - 65536];
    else if (t < 196608)  g_W[t] = rw[t - 131072];
    if (t < 256)          g_B[t] = lb[t];
    else if (t < 512)     g_B[t] = rb[t - 256];
    else if (t < 768)     g_B[t] = resb[t - 512];
}

// ---------------- SGEMM: C[M,Ncols] = A[M,256] * W[Ncols,256]^T + bias ------
__global__ void k_gemm(const float* __restrict__ A, const float* __restrict__ W,
                       const float* __restrict__ bias, float* __restrict__ C,
                       int M, int ldc) {
    __shared__ float As[16][132];
    __shared__ float Bs[16][132];
    int tid = threadIdx.x;
    int tx = tid & 15, ty = tid >> 4;
    int rowBase = blockIdx.y * 128;
    int colBase = blockIdx.x * 128;

    float c[8][8];
#pragma unroll
    for (int i = 0; i < 8; i++)
#pragma unroll
        for (int j = 0; j < 8; j++) c[i][j] = 0.0f;

    const float4* A4 = (const float4*)A;
    const float4* W4 = (const float4*)W;

    for (int kt = 0; kt < 256; kt += 16) {
#pragma unroll
        for (int l = 0; l < 2; l++) {
            int li = tid + l * 256;
            int rr = li >> 2, kq = li & 3;
            int gr = rowBase + rr;
            float4 v = make_float4(0.f, 0.f, 0.f, 0.f);
            if (gr < M) v = A4[gr * 64 + (kt >> 2) + kq];
            As[kq * 4 + 0][rr] = v.x; As[kq * 4 + 1][rr] = v.y;
            As[kq * 4 + 2][rr] = v.z; As[kq * 4 + 3][rr] = v.w;
            int gc = colBase + rr;
            float4 ww = W4[gc * 64 + (kt >> 2) + kq];
            Bs[kq * 4 + 0][rr] = ww.x; Bs[kq * 4 + 1][rr] = ww.y;
            Bs[kq * 4 + 2][rr] = ww.z; Bs[kq * 4 + 3][rr] = ww.w;
        }
        __syncthreads();
#pragma unroll
        for (int kk = 0; kk < 16; kk++) {
            float ra[8], rb[8];
#pragma unroll
            for (int i = 0; i < 8; i++) ra[i] = As[kk][ty * 8 + i];
#pragma unroll
            for (int j = 0; j < 8; j++) rb[j] = Bs[kk][tx * 8 + j];
#pragma unroll
            for (int i = 0; i < 8; i++)
#pragma unroll
                for (int j = 0; j < 8; j++) c[i][j] += ra[i] * rb[j];
        }
        __syncthreads();
    }
#pragma unroll
    for (int i = 0; i < 8; i++) {
        int r = rowBase + ty * 8 + i;
        if (r < M) {
#pragma unroll
            for (int j = 0; j < 8; j++) {
                int col = colBase + tx * 8 + j;
                C[r * ldc + col] = c[i][j] + bias[col];
            }
        }
    }
}

// ---------------- CSR build ----------------
__global__ void k_hist(const int* __restrict__ ei) {
    int t = blockIdx.x * blockDim.x + threadIdx.x;
    if (t < EE) atomicAdd(&g_deg[ei[EE + t]], 1);
}

__global__ void k_scan() {
    __shared__ int sh[1024];
    __shared__ int carry;
    int tid = threadIdx.x;
    if (tid == 0) carry = 0;
    __syncthreads();
    for (int base = 0; base < NN; base += 1024) {
        int i = base + tid;
        int v = (i < NN) ? g_deg[i] : 0;
        sh[tid] = v;
        __syncthreads();
        for (int o = 1; o < 1024; o <<= 1) {
            int t = (tid >= o) ? sh[tid - o] : 0;
            __syncthreads();
            sh[tid] += t;
            __syncthreads();
        }
        int incl = sh[tid];
        if (i < NN) g_off[i] = carry + incl - v;
        __syncthreads();
        if (tid == 1023) carry += incl;
        __syncthreads();
    }
}

__global__ void k_bucket(const int* __restrict__ ei) {
    int t = blockIdx.x * blockDim.x + threadIdx.x;
    if (t < EE) {
        int d = ei[EE + t];
        int p = atomicAdd(&g_cur[d], 1);
        g_bkt[g_off[d] + p] = t;
    }
}

// ------- per-node attention: online softmax + aggregate + LN + SiLU --------
__global__ void k_agg(const int* __restrict__ ei, const float* __restrict__ att,
                      const float* __restrict__ We, const float* __restrict__ cb,
                      const float* __restrict__ ng, const float* __restrict__ nb) {
    int gw = (blockIdx.x * blockDim.x + threadIdx.x) >> 5;
    int lane = threadIdx.x & 31;
    if (gw >= NN) return;
    int n = gw;
    int h = lane >> 3;

    float attv[8], we0[8], we1[8], we2[8], xr[8], acc[8];
#pragma unroll
    for (int k = 0; k < 8; k++) {
        int j = lane * 8 + k;
        attv[k] = att[j];
        we0[k] = We[j * 3]; we1[k] = We[j * 3 + 1]; we2[k] = We[j * 3 + 2];
        acc[k] = 0.0f;
    }
    const float4* xrp = (const float4*)&g_xlri[n * 768 + 256];
    {
        float4 a = xrp[lane * 2], b = xrp[lane * 2 + 1];
        xr[0] = a.x; xr[1] = a.y; xr[2] = a.z; xr[3] = a.w;
        xr[4] = b.x; xr[5] = b.y; xr[6] = b.z; xr[7] = b.w;
    }
    float nud0 = g_nuv[2 * n], nud1 = g_nuv[2 * n + 1];
    float m = -3.0e38f, s = 0.0f;
    int beg = g_off[n], end = g_off[n + 1];

    for (int i = beg; i < end; i++) {
        int e = g_bkt[i];
        int src = ei[e];
        float rx = nud0 - g_nuv[2 * src];
        float ry = nud1 - g_nuv[2 * src + 1];
        float dd = sqrtf(rx * rx + ry * ry);
        const float4* xp = (const float4*)&g_xlri[src * 768];
        float4 xa = xp[lane * 2], xb = xp[lane * 2 + 1];
        float xl[8] = {xa.x, xa.y, xa.z, xa.w, xb.x, xb.y, xb.z, xb.w};
        float pp = 0.0f;
#pragma unroll
        for (int k = 0; k < 8; k++) {
            float z = xl[k] + xr[k] + (rx * we0[k] + ry * we1[k] + dd * we2[k]);
            z = (z > 0.0f) ? z : 0.2f * z;
            pp += z * attv[k];
        }
        pp += __shfl_xor_sync(0xffffffffu, pp, 1);
        pp += __shfl_xor_sync(0xffffffffu, pp, 2);
        pp += __shfl_xor_sync(0xffffffffu, pp, 4);
        if ((lane & 7) == 0) g_logits[e * 4 + h] = pp;

        float mn = fmaxf(m, pp);
        float sc = expf(m - mn);
        float p = expf(pp - mn);
        s = s * sc + p;
        m = mn;
#pragma unroll
        for (int k = 0; k < 8; k++) acc[k] = acc[k] * sc + p * xl[k];
    }

    if ((lane & 7) == 0) { g_m[n * 4 + h] = m; g_s[n * 4 + h] = s; }

    float inv = (end > beg) ? (1.0f / s) : 0.0f;
    float o[8];
#pragma unroll
    for (int k = 0; k < 8; k++) o[k] = acc[k] * inv + cb[lane * 8 + k];

    // LN(256)
    float ps = 0.0f;
#pragma unroll
    for (int k = 0; k < 8; k++) ps += o[k];
    float mean = wsum(ps) * (1.0f / 256.0f);
    float pv = 0.0f;
#pragma unroll
    for (int k = 0; k < 8; k++) { float d = o[k] - mean; pv += d * d; }
    float var = wsum(pv) * (1.0f / 256.0f);
    float r = rsqrtf(var + 1e-5f);

    const float4* ip = (const float4*)&g_xlri[n * 768 + 512];
    float4 ia = ip[lane * 2], ib = ip[lane * 2 + 1];
    float idv[8] = {ia.x, ia.y, ia.z, ia.w, ib.x, ib.y, ib.z, ib.w};
#pragma unroll
    for (int k = 0; k < 8; k++) {
        int j = lane * 8 + k;
        float y = (o[k] - mean) * r * ng[j] + nb[j] + idv[k];
        y = y / (1.0f + expf(-y));
        g_pre[n * 256 + j] = y;
    }
}

// ---------------- alpha & edge_attr outputs ----------------
__global__ void k_alpha(const int* __restrict__ ei, float* __restrict__ out) {
    int t = blockIdx.x * blockDim.x + threadIdx.x;
    if (t < EE * 4) {
        int e = t >> 2, h = t & 3;
        int d = ei[EE + e];
        out[t] = expf(g_logits[t] - g_m[d * 4 + h]) / (g_s[d * 4 + h] + 1e-16f);
    }
}

__global__ void k_eattr(const int* __restrict__ ei, float* __restrict__ out) {
    int t = blockIdx.x * blockDim.x + threadIdx.x;
    if (t < EE) {
        int sN = ei[t], d = ei[EE + t];
        float rx = g_nuv[2 * d] - g_nuv[2 * sN];
        float ry = g_nuv[2 * d + 1] - g_nuv[2 * sN + 1];
        out[t * 3]     = rx;
        out[t * 3 + 1] = ry;
        out[t * 3 + 2] = sqrtf(rx * rx + ry * ry);
    }
}

// ---------------- host launcher ----------------
extern "C" void kernel_launch(void* const* d_in, const int* in_sizes, int n_in,
                              void* d_out, int out_size) {
    const float* x      = (const float*)d_in[0];
    const float* kpts   = (const float*)d_in[1];
    const float* pts3d  = (const float*)d_in[2];
    const float* pe_w1  = (const float*)d_in[3];
    const float* pe_b1  = (const float*)d_in[4];
    const float* pe_g1  = (const float*)d_in[5];
    const float* pe_bn1 = (const float*)d_in[6];
    const float* pe_w2  = (const float*)d_in[7];
    const float* pe_b2  = (const float*)d_in[8];
    const float* pe_g2  = (const float*)d_in[9];
    const float* pe_bn2 = (const float*)d_in[10];
    const float* lin_l_w = (const float*)d_in[11];
    const float* lin_l_b = (const float*)d_in[12];
    const float* lin_r_w = (const float*)d_in[13];
    const float* lin_r_b = (const float*)d_in[14];
    const float* lin_edge_w = (const float*)d_in[15];
    const float* att    = (const float*)d_in[16];
    const float* conv_b = (const float*)d_in[17];
    const float* norm_g = (const float*)d_in[18];
    const float* norm_b = (const float*)d_in[19];
    const float* res_w  = (const float*)d_in[20];
    const float* res_b  = (const float*)d_in[21];
    const float* proj_w = (const float*)d_in[22];
    const float* proj_b = (const float*)d_in[23];
    const int*   ei     = (const int*)d_in[24];
    float* out = (float*)d_out;

    k_init<<<(NN + 255) / 256, 256>>>();
    k_node<<<(NN + 7) / 8, 256>>>(x, kpts, pts3d, pe_w1, pe_b1, pe_g1, pe_bn1,
                                  pe_w2, pe_b2, pe_g2, pe_bn2);
    k_concat<<<(196608 + 255) / 256, 256>>>(lin_l_w, lin_r_w, res_w,
                                            lin_l_b, lin_r_b, res_b);

    float* dW; cudaGetSymbolAddress((void**)&dW, g_W);
    float* dB; cudaGetSymbolAddress((void**)&dB, g_B);
    float* dXC; cudaGetSymbolAddress((void**)&dXC, g_xcomb);
    float* dXLRI; cudaGetSymbolAddress((void**)&dXLRI, g_xlri);
    float* dPRE; cudaGetSymbolAddress((void**)&dPRE, g_pre);

    // x_l | x_r | identity in one GEMM
    k_gemm<<<dim3(6, (NN + 127) / 128), 256>>>(dXC, dW, dB, dXLRI, NN, 768);

    k_hist<<<(EE + 255) / 256, 256>>>(ei);
    k_scan<<<1, 1024>>>();
    k_bucket<<<(EE + 255) / 256, 256>>>(ei);

    k_agg<<<(NN + 7) / 8, 256>>>(ei, att, lin_edge_w, conv_b, norm_g, norm_b);

    if (out_size >= NN * 256 + EE * 4)
        k_alpha<<<(EE * 4 + 255) / 256, 256>>>(ei, out + NN * 256);
    if (out_size >= NN * 256 + EE * 4 + EE * 3)
        k_eattr<<<(EE + 255) / 256, 256>>>(ei, out + NN * 256 + EE * 4);

    // final projection
    k_gemm<<<dim3(2, (NN + 127) / 128), 256>>>(dPRE, proj_w, proj_b, out, NN, 256);
}

// round 3
// speedup vs baseline: 1.4594x; 1.4594x over previous
#include <cuda_runtime.h>
#include <cuda_bf16.h>
#include <math.h>
#include <stdint.h>

#define NN 50000
#define EE 800000
#define XD 192
#define MPAD 50048
#define KB 768          // split-K: [hi | hi | lo] x 256

// ---------------- scratch ----------------
static __device__ __nv_bfloat16 g_Abig[(size_t)MPAD * KB];   // A' splits
static __device__ __nv_bfloat16 g_Wbig[768 * KB];            // W' gemm1 (ll|lr|res)
static __device__ __nv_bfloat16 g_W2big[256 * KB];           // W' gemm2 (proj)
static __device__ float g_B[768];
static __device__ float g_nuv[NN * 2];
static __device__ float g_xlri[(size_t)NN * 768];            // x_l | x_r | identity
static __device__ float g_logits[EE * 4];
static __device__ float g_m[NN * 4];
static __device__ float g_s[NN * 4];
static __device__ int   g_deg[NN];
static __device__ int   g_cur[NN];
static __device__ int   g_off[NN + 1];
static __device__ int   g_bkt[EE];
static __device__ int   g_bsum[256];

__device__ __forceinline__ float wsum(float v) {
#pragma unroll
    for (int o = 16; o > 0; o >>= 1) v += __shfl_xor_sync(0xffffffffu, v, o);
    return v;
}

__device__ __forceinline__ void write3(int n, int j, float v) {
    __nv_bfloat16 h = __float2bfloat16(v);
    float r = v - __bfloat162float(h);
    __nv_bfloat16 l = __float2bfloat16(r);
    size_t base = (size_t)n * KB;
    g_Abig[base + j]       = h;
    g_Abig[base + 256 + j] = h;
    g_Abig[base + 512 + j] = l;
}

__device__ __forceinline__ uint32_t s2u(const void* p) {
    uint32_t a;
    asm("{ .reg .u64 t; cvta.to.shared.u64 t, %1; cvt.u32.u64 %0, t; }" : "=r"(a) : "l"(p));
    return a;
}

// ---------------- init ----------------
__global__ void k_init() {
    int t = blockIdx.x * blockDim.x + threadIdx.x;
    if (t < NN) { g_deg[t] = 0; g_cur[t] = 0; }
}

// ---------------- pos encoder + A' assembly (1 warp / node) ----------------
__global__ void k_node(const float* __restrict__ x, const float* __restrict__ kpts,
                       const float* __restrict__ pts3d,
                       const float* __restrict__ w1, const float* __restrict__ b1,
                       const float* __restrict__ g1, const float* __restrict__ bn1,
                       const float* __restrict__ w2, const float* __restrict__ b2,
                       const float* __restrict__ g2, const float* __restrict__ bn2) {
    int gw = (blockIdx.x * blockDim.x + threadIdx.x) >> 5;
    int lane = threadIdx.x & 31;
    int w = threadIdx.x >> 5;
    if (gw >= NN) return;
    int n = gw;

    float nu = kpts[n * 2]     * (1.0f / 1216.0f);
    float nv = kpts[n * 2 + 1] * (1.0f / 352.0f);
    float dep = pts3d[n * 3 + 2];
    dep = fminf(fmaxf(dep, 0.1f), 100.0f);

    float h = nu * w1[lane * 3] + nv * w1[lane * 3 + 1] + dep * w1[lane * 3 + 2] + b1[lane];
    float mu = wsum(h) * (1.0f / 32.0f);
    float d = h - mu;
    float var = wsum(d * d) * (1.0f / 32.0f);
    float y = d * rsqrtf(var + 1e-5f) * g1[lane] + bn1[lane];
    y = y / (1.0f + expf(-y));

    __shared__ float sh[8][32];
    sh[w][lane] = y;
    __syncwarp();

    float o0 = b2[lane], o1 = b2[lane + 32];
#pragma unroll
    for (int j = 0; j < 32; j++) {
        float hv = sh[w][j];
        o0 += hv * w2[lane * 32 + j];
        o1 += hv * w2[(lane + 32) * 32 + j];
    }
    float mean = wsum(o0 + o1) * (1.0f / 64.0f);
    float d0 = o0 - mean, d1 = o1 - mean;
    float v2 = wsum(d0 * d0 + d1 * d1) * (1.0f / 64.0f);
    float r = rsqrtf(v2 + 1e-5f);
    float p0 = d0 * r * g2[lane] + bn2[lane];
    float p1 = d1 * r * g2[lane + 32] + bn2[lane + 32];

#pragma unroll
    for (int i = 0; i < 6; i++) write3(n, lane + i * 32, x[n * XD + lane + i * 32]);
    write3(n, 192 + lane, p0);
    write3(n, 224 + lane, p1);

    if (lane == 0) { g_nuv[2 * n] = nu; g_nuv[2 * n + 1] = nv; }
}

// ---------------- weight splits ----------------
__global__ void k_concat(const float* ll, const float* lr, const float* rw,
                         const float* lb, const float* rb, const float* resb) {
    int t = blockIdx.x * blockDim.x + threadIdx.x;
    if (t < 196608) {
        float v;
        if (t < 65536)       v = ll[t];
        else if (t < 131072) v = lr[t - 65536];
        else                 v = rw[t - 131072];
        int row = t >> 8, col = t & 255;
        __nv_bfloat16 h = __float2bfloat16(v);
        __nv_bfloat16 l = __float2bfloat16(v - __bfloat162float(h));
        g_Wbig[row * KB + col]       = h;
        g_Wbig[row * KB + 256 + col] = l;   // pairs with A seg1 (hi)
        g_Wbig[row * KB + 512 + col] = h;   // pairs with A seg2 (lo)
    }
    if (t < 256)       g_B[t] = lb[t];
    else if (t < 512)  g_B[t] = rb[t - 256];
    else if (t < 768)  g_B[t] = resb[t - 512];
}

__global__ void k_splitW2(const float* pw) {
    int t = blockIdx.x * blockDim.x + threadIdx.x;
    if (t < 65536) {
        float v = pw[t];
        int row = t >> 8, col = t & 255;
        __nv_bfloat16 h = __float2bfloat16(v);
        __nv_bfloat16 l = __float2bfloat16(v - __bfloat162float(h));
        g_W2big[row * KB + col]       = h;
        g_W2big[row * KB + 256 + col] = l;
        g_W2big[row * KB + 512 + col] = h;
    }
}

// -------- mma.sync bf16 GEMM: C[M,*] = A'[M,768] * W'[Ncols,768]^T + bias --------
// CTA 128x128, 8 warps (2x4), warp 64x32, K-chunks of 64, cp.async double buffer.
#define SSTRIDE 72    // halves per smem row (144 B, conflict-free)
#define ABYTES  18432 // 128*72*2
__global__ void __launch_bounds__(256, 2) k_mgemm(const __nv_bfloat16* __restrict__ A,
                                                  const __nv_bfloat16* __restrict__ Bw,
                                                  const float* __restrict__ bias,
                                                  float* __restrict__ C, int M, int ldc) {
    extern __shared__ __align__(16) char smem[];
    const int tid = threadIdx.x, wid = tid >> 5, lane = tid & 31;
    const int mBase = blockIdx.y * 128;
    const int nBase = blockIdx.x * 128;
    const uint32_t sb = s2u(smem);
    const uint32_t sA[2] = {sb, sb + ABYTES};
    const uint32_t sB[2] = {sb + 2 * ABYTES, sb + 3 * ABYTES};

    const int wm = wid & 1;        // 0..1 (M)
    const int wn = wid >> 1;       // 0..3 (N)
    const int grp = lane >> 3;     // 0..3
    const int l8 = lane & 7;

    // cp.async source/dest base (per thread: 4 A segs, 4 B segs per chunk)
    const int ldRow = tid >> 3;          // 0..31 step base; rows covered: tid>>3 + i*32
    const int ldSeg = tid & 7;

    float c[4][4][4];
#pragma unroll
    for (int mt = 0; mt < 4; mt++)
#pragma unroll
        for (int nt = 0; nt < 4; nt++)
#pragma unroll
            for (int q = 0; q < 4; q++) c[mt][nt][q] = 0.0f;

    // ldmatrix address bases (at kstep 0 inside a chunk buffer)
    // A mtile mt: row = wm*64 + mt*16 + (grp&1)*8 + l8 ; colByte = (grp>>1)*16
    uint32_t aAddr[4];
#pragma unroll
    for (int mt = 0; mt < 4; mt++) {
        int row = wm * 64 + mt * 16 + (grp & 1) * 8 + l8;
        aAddr[mt] = (uint32_t)(row * (SSTRIDE * 2) + (grp >> 1) * 16);
    }
    // B pair p (ntiles 2p,2p+1): nrow = wn*32 + (2p + (grp>>1))*8 + l8 ; colByte = (grp&1)*16
    uint32_t bAddr[2];
#pragma unroll
    for (int p = 0; p < 2; p++) {
        int nrow = wn * 32 + (2 * p + (grp >> 1)) * 8 + l8;
        bAddr[p] = (uint32_t)(nrow * (SSTRIDE * 2) + (grp & 1) * 16);
    }

    // preload chunk 0
    {
        const int b = 0, ch = 0;
#pragma unroll
        for (int i = 0; i < 4; i++) {
            int row = ldRow + i * 32;
            uint32_t sa = sA[b] + (uint32_t)(row * (SSTRIDE * 2) + ldSeg * 16);
            const __nv_bfloat16* ga = A + (size_t)(mBase + row) * KB + ch * 64 + ldSeg * 8;
            asm volatile("cp.async.cg.shared.global [%0], [%1], 16;" :: "r"(sa), "l"(ga));
            uint32_t sbb = sB[b] + (uint32_t)(row * (SSTRIDE * 2) + ldSeg * 16);
            const __nv_bfloat16* gb = Bw + (size_t)(nBase + row) * KB + ch * 64 + ldSeg * 8;
            asm volatile("cp.async.cg.shared.global [%0], [%1], 16;" :: "r"(sbb), "l"(gb));
        }
        asm volatile("cp.async.commit_group;" ::: "memory");
    }

    for (int ch = 0; ch < 12; ch++) {
        int b = ch & 1;
        if (ch + 1 < 12) {
            int nb = (ch + 1) & 1;
#pragma unroll
            for (int i = 0; i < 4; i++) {
                int row = ldRow + i * 32;
                uint32_t sa = sA[nb] + (uint32_t)(row * (SSTRIDE * 2) + ldSeg * 16);
                const __nv_bfloat16* ga = A + (size_t)(mBase + row) * KB + (ch + 1) * 64 + ldSeg * 8;
                asm volatile("cp.async.cg.shared.global [%0], [%1], 16;" :: "r"(sa), "l"(ga));
                uint32_t sbb = sB[nb] + (uint32_t)(row * (SSTRIDE * 2) + ldSeg * 16);
                const __nv_bfloat16* gb = Bw + (size_t)(nBase + row) * KB + (ch + 1) * 64 + ldSeg * 8;
                asm volatile("cp.async.cg.shared.global [%0], [%1], 16;" :: "r"(sbb), "l"(gb));
            }
            asm volatile("cp.async.commit_group;" ::: "memory");
            asm volatile("cp.async.wait_group 1;" ::: "memory");
        } else {
            asm volatile("cp.async.wait_group 0;" ::: "memory");
        }
        __syncthreads();

#pragma unroll
        for (int ks = 0; ks < 4; ks++) {
            uint32_t a[4][4], bb[4][2];
#pragma unroll
            for (int mt = 0; mt < 4; mt++) {
                uint32_t addr = sA[b] + aAddr[mt] + ks * 32;
                asm volatile("ldmatrix.sync.aligned.m8n8.x4.shared.b16 {%0,%1,%2,%3}, [%4];"
                             : "=r"(a[mt][0]), "=r"(a[mt][1]), "=r"(a[mt][2]), "=r"(a[mt][3])
                             : "r"(addr));
            }
#pragma unroll
            for (int p = 0; p < 2; p++) {
                uint32_t addr = sB[b] + bAddr[p] + ks * 32;
                asm volatile("ldmatrix.sync.aligned.m8n8.x4.shared.b16 {%0,%1,%2,%3}, [%4];"
                             : "=r"(bb[2 * p][0]), "=r"(bb[2 * p][1]),
                               "=r"(bb[2 * p + 1][0]), "=r"(bb[2 * p + 1][1])
                             : "r"(addr));
            }
#pragma unroll
            for (int mt = 0; mt < 4; mt++)
#pragma unroll
                for (int nt = 0; nt < 4; nt++) {
                    asm volatile(
                        "mma.sync.aligned.m16n8k16.row.col.f32.bf16.bf16.f32 "
                        "{%0,%1,%2,%3}, {%4,%5,%6,%7}, {%8,%9}, {%0,%1,%2,%3};"
                        : "+f"(c[mt][nt][0]), "+f"(c[mt][nt][1]),
                          "+f"(c[mt][nt][2]), "+f"(c[mt][nt][3])
                        : "r"(a[mt][0]), "r"(a[mt][1]), "r"(a[mt][2]), "r"(a[mt][3]),
                          "r"(bb[nt][0]), "r"(bb[nt][1]));
                }
        }
        __syncthreads();
    }

    // epilogue with bias
#pragma unroll
    for (int mt = 0; mt < 4; mt++) {
        int r0 = mBase + wm * 64 + mt * 16 + (lane >> 2);
        int r1 = r0 + 8;
#pragma unroll
        for (int nt = 0; nt < 4; nt++) {
            int col = nBase + wn * 32 + nt * 8 + (lane & 3) * 2;
            float b0 = bias[col], b1 = bias[col + 1];
            if (r0 < M) {
                float2 v = make_float2(c[mt][nt][0] + b0, c[mt][nt][1] + b1);
                *reinterpret_cast<float2*>(C + (size_t)r0 * ldc + col) = v;
            }
            if (r1 < M) {
                float2 v = make_float2(c[mt][nt][2] + b0, c[mt][nt][3] + b1);
                *reinterpret_cast<float2*>(C + (size_t)r1 * ldc + col) = v;
            }
        }
    }
}

// ---------------- CSR build ----------------
__global__ void k_hist(const int* __restrict__ ei) {
    int t = blockIdx.x * blockDim.x + threadIdx.x;
    if (t < EE) atomicAdd(&g_deg[ei[EE + t]], 1);
}

__global__ void k_scan1() {
    __shared__ int sh[256];
    int b = blockIdx.x, tid = threadIdx.x;
    int i = b * 256 + tid;
    int v = (i < NN) ? g_deg[i] : 0;
    sh[tid] = v;
    __syncthreads();
    for (int o = 1; o < 256; o <<= 1) {
        int t = (tid >= o) ? sh[tid - o] : 0;
        __syncthreads();
        sh[tid] += t;
        __syncthreads();
    }
    if (i < NN) g_off[i] = sh[tid] - v;
    if (tid == 255) g_bsum[b] = sh[255];
}

__global__ void k_scan2() {
    __shared__ int sh[256];
    int tid = threadIdx.x;
    int v = (tid < 196) ? g_bsum[tid] : 0;
    sh[tid] = v;
    __syncthreads();
    for (int o = 1; o < 256; o <<= 1) {
        int t = (tid >= o) ? sh[tid - o] : 0;
        __syncthreads();
        sh[tid] += t;
        __syncthreads();
    }
    g_bsum[tid] = sh[tid] - v;
}

__global__ void k_scan3() {
    int i = blockIdx.x * 256 + threadIdx.x;
    if (i < NN) g_off[i] += g_bsum[blockIdx.x];
    if (i == 0) g_off[NN] = EE;
}

__global__ void k_bucket(const int* __restrict__ ei) {
    int t = blockIdx.x * blockDim.x + threadIdx.x;
    if (t < EE) {
        int d = ei[EE + t];
        int p = atomicAdd(&g_cur[d], 1);
        g_bkt[g_off[d] + p] = t;
    }
}

// ------- per-node attention: online softmax + aggregate + LN + SiLU + split --------
__global__ void k_agg(const int* __restrict__ ei, const float* __restrict__ att,
                      const float* __restrict__ We, const float* __restrict__ cb,
                      const float* __restrict__ ng, const float* __restrict__ nb) {
    int gw = (blockIdx.x * blockDim.x + threadIdx.x) >> 5;
    int lane = threadIdx.x & 31;
    if (gw >= NN) return;
    int n = gw;
    int h = lane >> 3;

    float attv[8], we0[8], we1[8], we2[8], xr[8], acc[8];
#pragma unroll
    for (int k = 0; k < 8; k++) {
        int j = lane * 8 + k;
        attv[k] = att[j];
        we0[k] = We[j * 3]; we1[k] = We[j * 3 + 1]; we2[k] = We[j * 3 + 2];
        acc[k] = 0.0f;
    }
    const float4* xrp = (const float4*)&g_xlri[(size_t)n * 768 + 256];
    {
        float4 a = xrp[lane * 2], b = xrp[lane * 2 + 1];
        xr[0] = a.x; xr[1] = a.y; xr[2] = a.z; xr[3] = a.w;
        xr[4] = b.x; xr[5] = b.y; xr[6] = b.z; xr[7] = b.w;
    }
    float nud0 = g_nuv[2 * n], nud1 = g_nuv[2 * n + 1];
    float m = -3.0e38f, s = 0.0f;
    int beg = g_off[n], end = g_off[n + 1];

    for (int i = beg; i < end; i++) {
        int e = g_bkt[i];
        int src = ei[e];
        float rx = nud0 - g_nuv[2 * src];
        float ry = nud1 - g_nuv[2 * src + 1];
        float dd = sqrtf(rx * rx + ry * ry);
        const float4* xp = (const float4*)&g_xlri[(size_t)src * 768];
        float4 xa = xp[lane * 2], xb = xp[lane * 2 + 1];
        float xl[8] = {xa.x, xa.y, xa.z, xa.w, xb.x, xb.y, xb.z, xb.w};
        float pp = 0.0f;
#pragma unroll
        for (int k = 0; k < 8; k++) {
            float z = xl[k] + xr[k] + (rx * we0[k] + ry * we1[k] + dd * we2[k]);
            z = (z > 0.0f) ? z : 0.2f * z;
            pp += z * attv[k];
        }
        pp += __shfl_xor_sync(0xffffffffu, pp, 1);
        pp += __shfl_xor_sync(0xffffffffu, pp, 2);
        pp += __shfl_xor_sync(0xffffffffu, pp, 4);
        if ((lane & 7) == 0) g_logits[e * 4 + h] = pp;

        float mn = fmaxf(m, pp);
        float sc = expf(m - mn);
        float p = expf(pp - mn);
        s = s * sc + p;
        m = mn;
#pragma unroll
        for (int k = 0; k < 8; k++) acc[k] = acc[k] * sc + p * xl[k];
    }

    if ((lane & 7) == 0) { g_m[n * 4 + h] = m; g_s[n * 4 + h] = s; }

    float inv = (end > beg) ? (1.0f / s) : 0.0f;
    float o[8];
#pragma unroll
    for (int k = 0; k < 8; k++) o[k] = acc[k] * inv + cb[lane * 8 + k];

    float ps = 0.0f;
#pragma unroll
    for (int k = 0; k < 8; k++) ps += o[k];
    float mean = wsum(ps) * (1.0f / 256.0f);
    float pv = 0.0f;
#pragma unroll
    for (int k = 0; k < 8; k++) { float d = o[k] - mean; pv += d * d; }
    float var = wsum(pv) * (1.0f / 256.0f);
    float r = rsqrtf(var + 1e-5f);

    const float4* ip = (const float4*)&g_xlri[(size_t)n * 768 + 512];
    float4 ia = ip[lane * 2], ib = ip[lane * 2 + 1];
    float idv[8] = {ia.x, ia.y, ia.z, ia.w, ib.x, ib.y, ib.z, ib.w};
#pragma unroll
    for (int k = 0; k < 8; k++) {
        int j = lane * 8 + k;
        float y = (o[k] - mean) * r * ng[j] + nb[j] + idv[k];
        y = y / (1.0f + expf(-y));
        write3(n, j, y);
    }
}

// ---------------- alpha & edge_attr outputs ----------------
__global__ void k_alpha(const int* __restrict__ ei, float* __restrict__ out) {
    int t = blockIdx.x * blockDim.x + threadIdx.x;
    if (t < EE * 4) {
        int e = t >> 2, h = t & 3;
        int d = ei[EE + e];
        out[t] = expf(g_logits[t] - g_m[d * 4 + h]) / (g_s[d * 4 + h] + 1e-16f);
    }
}

__global__ void k_eattr(const int* __restrict__ ei, float* __restrict__ out) {
    int t = blockIdx.x * blockDim.x + threadIdx.x;
    if (t < EE) {
        int sN = ei[t], d = ei[EE + t];
        float rx = g_nuv[2 * d] - g_nuv[2 * sN];
        float ry = g_nuv[2 * d + 1] - g_nuv[2 * sN + 1];
        out[t * 3]     = rx;
        out[t * 3 + 1] = ry;
        out[t * 3 + 2] = sqrtf(rx * rx + ry * ry);
    }
}

// ---------------- host launcher ----------------
extern "C" void kernel_launch(void* const* d_in, const int* in_sizes, int n_in,
                              void* d_out, int out_size) {
    const float* x      = (const float*)d_in[0];
    const float* kpts   = (const float*)d_in[1];
    const float* pts3d  = (const float*)d_in[2];
    const float* pe_w1  = (const float*)d_in[3];
    const float* pe_b1  = (const float*)d_in[4];
    const float* pe_g1  = (const float*)d_in[5];
    const float* pe_bn1 = (const float*)d_in[6];
    const float* pe_w2  = (const float*)d_in[7];
    const float* pe_b2  = (const float*)d_in[8];
    const float* pe_g2  = (const float*)d_in[9];
    const float* pe_bn2 = (const float*)d_in[10];
    const float* lin_l_w = (const float*)d_in[11];
    const float* lin_l_b = (const float*)d_in[12];
    const float* lin_r_w = (const float*)d_in[13];
    const float* lin_r_b = (const float*)d_in[14];
    const float* lin_edge_w = (const float*)d_in[15];
    const float* att    = (const float*)d_in[16];
    const float* conv_b = (const float*)d_in[17];
    const float* norm_g = (const float*)d_in[18];
    const float* norm_b = (const float*)d_in[19];
    const float* res_w  = (const float*)d_in[20];
    const float* res_b  = (const float*)d_in[21];
    const float* proj_w = (const float*)d_in[22];
    const float* proj_b = (const float*)d_in[23];
    const int*   ei     = (const int*)d_in[24];
    float* out = (float*)d_out;

    cudaFuncSetAttribute(k_mgemm, cudaFuncAttributeMaxDynamicSharedMemorySize, 4 * ABYTES);

    __nv_bfloat16* dA;  cudaGetSymbolAddress((void**)&dA,  g_Abig);
    __nv_bfloat16* dW;  cudaGetSymbolAddress((void**)&dW,  g_Wbig);
    __nv_bfloat16* dW2; cudaGetSymbolAddress((void**)&dW2, g_W2big);
    float* dB;    cudaGetSymbolAddress((void**)&dB,   g_B);
    float* dXLRI; cudaGetSymbolAddress((void**)&dXLRI, g_xlri);

    k_init<<<(NN + 255) / 256, 256>>>();
    k_node<<<(NN + 7) / 8, 256>>>(x, kpts, pts3d, pe_w1, pe_b1, pe_g1, pe_bn1,
                                  pe_w2, pe_b2, pe_g2, pe_bn2);
    k_concat<<<768, 256>>>(lin_l_w, lin_r_w, res_w, lin_l_b, lin_r_b, res_b);
    k_splitW2<<<256, 256>>>(proj_w);

    // gemm1: x_l | x_r | identity
    k_mgemm<<<dim3(6, 391), 256, 4 * ABYTES>>>(dA, dW, dB, dXLRI, NN, 768);

    k_hist<<<(EE + 255) / 256, 256>>>(ei);
    k_scan1<<<196, 256>>>();
    k_scan2<<<1, 256>>>();
    k_scan3<<<196, 256>>>();
    k_bucket<<<(EE + 255) / 256, 256>>>(ei);

    k_agg<<<(NN + 7) / 8, 256>>>(ei, att, lin_edge_w, conv_b, norm_g, norm_b);

    if (out_size >= NN * 256 + EE * 4)
        k_alpha<<<(EE * 4 + 255) / 256, 256>>>(ei, out + NN * 256);
    if (out_size >= NN * 256 + EE * 4 + EE * 3)
        k_eattr<<<(EE + 255) / 256, 256>>>(ei, out + NN * 256 + EE * 4);

    // gemm2: final projection
    k_mgemm<<<dim3(2, 391), 256, 4 * ABYTES>>>(dA, dW2, proj_b, out, NN, 256);
}

// round 4
// speedup vs baseline: 1.5978x; 1.0948x over previous
#include <cuda_runtime.h>
#include <cuda_bf16.h>
#include <math.h>
#include <stdint.h>

#define NN 50000
#define EE 800000
#define XD 192
#define MPAD 50048
#define KB 768          // split-K: [hi | hi | lo] x 256

// ---------------- scratch ----------------
static __device__ __nv_bfloat16 g_Abig[(size_t)MPAD * KB];   // A' splits
static __device__ __nv_bfloat16 g_Wbig[768 * KB];            // W' gemm1 (ll|lr|res)
static __device__ __nv_bfloat16 g_W2big[256 * KB];           // W' gemm2 (proj)
static __device__ float g_B[768];
static __device__ float g_nuv[NN * 2];
static __device__ float g_xlri[(size_t)NN * 768];            // x_l | x_r | identity
static __device__ float g_logits[EE * 4];                    // bucket-ordered
static __device__ float4 g_bgeo[EE];                         // (rx, ry, dist, src-bits)
static __device__ float g_m[NN * 4];
static __device__ float g_s[NN * 4];
static __device__ int   g_deg[NN];
static __device__ int   g_cur[NN];
static __device__ int   g_off[NN + 1];
static __device__ int   g_bkt[EE];
static __device__ int   g_bsum[256];

__device__ __forceinline__ float wsum(float v) {
#pragma unroll
    for (int o = 16; o > 0; o >>= 1) v += __shfl_xor_sync(0xffffffffu, v, o);
    return v;
}

__device__ __forceinline__ void write3(int n, int j, float v) {
    __nv_bfloat16 h = __float2bfloat16(v);
    float r = v - __bfloat162float(h);
    __nv_bfloat16 l = __float2bfloat16(r);
    size_t base = (size_t)n * KB;
    g_Abig[base + j]       = h;
    g_Abig[base + 256 + j] = h;
    g_Abig[base + 512 + j] = l;
}

__device__ __forceinline__ uint32_t s2u(const void* p) {
    uint32_t a;
    asm("{ .reg .u64 t; cvta.to.shared.u64 t, %1; cvt.u32.u64 %0, t; }" : "=r"(a) : "l"(p));
    return a;
}

// ---------------- init ----------------
__global__ void k_init() {
    int t = blockIdx.x * blockDim.x + threadIdx.x;
    if (t < NN) { g_deg[t] = 0; g_cur[t] = 0; }
}

// ---------------- pos encoder + A' assembly (1 warp / node) ----------------
__global__ void k_node(const float* __restrict__ x, const float* __restrict__ kpts,
                       const float* __restrict__ pts3d,
                       const float* __restrict__ w1, const float* __restrict__ b1,
                       const float* __restrict__ g1, const float* __restrict__ bn1,
                       const float* __restrict__ w2, const float* __restrict__ b2,
                       const float* __restrict__ g2, const float* __restrict__ bn2) {
    int gw = (blockIdx.x * blockDim.x + threadIdx.x) >> 5;
    int lane = threadIdx.x & 31;
    int w = threadIdx.x >> 5;
    if (gw >= NN) return;
    int n = gw;

    float nu = kpts[n * 2]     * (1.0f / 1216.0f);
    float nv = kpts[n * 2 + 1] * (1.0f / 352.0f);
    float dep = pts3d[n * 3 + 2];
    dep = fminf(fmaxf(dep, 0.1f), 100.0f);

    float h = nu * w1[lane * 3] + nv * w1[lane * 3 + 1] + dep * w1[lane * 3 + 2] + b1[lane];
    float mu = wsum(h) * (1.0f / 32.0f);
    float d = h - mu;
    float var = wsum(d * d) * (1.0f / 32.0f);
    float y = d * rsqrtf(var + 1e-5f) * g1[lane] + bn1[lane];
    y = y / (1.0f + __expf(-y));

    __shared__ float sh[8][32];
    sh[w][lane] = y;
    __syncwarp();

    float o0 = b2[lane], o1 = b2[lane + 32];
#pragma unroll
    for (int j = 0; j < 32; j++) {
        float hv = sh[w][j];
        o0 += hv * w2[lane * 32 + j];
        o1 += hv * w2[(lane + 32) * 32 + j];
    }
    float mean = wsum(o0 + o1) * (1.0f / 64.0f);
    float d0 = o0 - mean, d1 = o1 - mean;
    float v2 = wsum(d0 * d0 + d1 * d1) * (1.0f / 64.0f);
    float r = rsqrtf(v2 + 1e-5f);
    float p0 = d0 * r * g2[lane] + bn2[lane];
    float p1 = d1 * r * g2[lane + 32] + bn2[lane + 32];

#pragma unroll
    for (int i = 0; i < 6; i++) write3(n, lane + i * 32, x[n * XD + lane + i * 32]);
    write3(n, 192 + lane, p0);
    write3(n, 224 + lane, p1);

    if (lane == 0) { g_nuv[2 * n] = nu; g_nuv[2 * n + 1] = nv; }
}

// ---------------- weight splits ----------------
__global__ void k_concat(const float* ll, const float* lr, const float* rw,
                         const float* lb, const float* rb, const float* resb) {
    int t = blockIdx.x * blockDim.x + threadIdx.x;
    if (t < 196608) {
        float v;
        if (t < 65536)       v = ll[t];
        else if (t < 131072) v = lr[t - 65536];
        else                 v = rw[t - 131072];
        int row = t >> 8, col = t & 255;
        __nv_bfloat16 h = __float2bfloat16(v);
        __nv_bfloat16 l = __float2bfloat16(v - __bfloat162float(h));
        g_Wbig[row * KB + col]       = h;
        g_Wbig[row * KB + 256 + col] = l;
        g_Wbig[row * KB + 512 + col] = h;
    }
    if (t < 256)       g_B[t] = lb[t];
    else if (t < 512)  g_B[t] = rb[t - 256];
    else if (t < 768)  g_B[t] = resb[t - 512];
}

__global__ void k_splitW2(const float* pw) {
    int t = blockIdx.x * blockDim.x + threadIdx.x;
    if (t < 65536) {
        float v = pw[t];
        int row = t >> 8, col = t & 255;
        __nv_bfloat16 h = __float2bfloat16(v);
        __nv_bfloat16 l = __float2bfloat16(v - __bfloat162float(h));
        g_W2big[row * KB + col]       = h;
        g_W2big[row * KB + 256 + col] = l;
        g_W2big[row * KB + 512 + col] = h;
    }
}

// -------- mma.sync bf16 GEMM: C[M,*] = A'[M,768] * W'[Ncols,768]^T + bias --------
#define SSTRIDE 72
#define ABYTES  18432
__global__ void __launch_bounds__(256, 2) k_mgemm(const __nv_bfloat16* __restrict__ A,
                                                  const __nv_bfloat16* __restrict__ Bw,
                                                  const float* __restrict__ bias,
                                                  float* __restrict__ C, int M, int ldc) {
    extern __shared__ __align__(16) char smem[];
    const int tid = threadIdx.x, wid = tid >> 5, lane = tid & 31;
    const int mBase = blockIdx.y * 128;
    const int nBase = blockIdx.x * 128;
    const uint32_t sb = s2u(smem);
    const uint32_t sA[2] = {sb, sb + ABYTES};
    const uint32_t sB[2] = {sb + 2 * ABYTES, sb + 3 * ABYTES};

    const int wm = wid & 1;
    const int wn = wid >> 1;
    const int grp = lane >> 3;
    const int l8 = lane & 7;
    const int ldRow = tid >> 3;
    const int ldSeg = tid & 7;

    float c[4][4][4];
#pragma unroll
    for (int mt = 0; mt < 4; mt++)
#pragma unroll
        for (int nt = 0; nt < 4; nt++)
#pragma unroll
            for (int q = 0; q < 4; q++) c[mt][nt][q] = 0.0f;

    uint32_t aAddr[4];
#pragma unroll
    for (int mt = 0; mt < 4; mt++) {
        int row = wm * 64 + mt * 16 + (grp & 1) * 8 + l8;
        aAddr[mt] = (uint32_t)(row * (SSTRIDE * 2) + (grp >> 1) * 16);
    }
    uint32_t bAddr[2];
#pragma unroll
    for (int p = 0; p < 2; p++) {
        int nrow = wn * 32 + (2 * p + (grp >> 1)) * 8 + l8;
        bAddr[p] = (uint32_t)(nrow * (SSTRIDE * 2) + (grp & 1) * 16);
    }

    {
        const int b = 0, ch = 0;
#pragma unroll
        for (int i = 0; i < 4; i++) {
            int row = ldRow + i * 32;
            uint32_t sa = sA[b] + (uint32_t)(row * (SSTRIDE * 2) + ldSeg * 16);
            const __nv_bfloat16* ga = A + (size_t)(mBase + row) * KB + ch * 64 + ldSeg * 8;
            asm volatile("cp.async.cg.shared.global [%0], [%1], 16;" :: "r"(sa), "l"(ga));
            uint32_t sbb = sB[b] + (uint32_t)(row * (SSTRIDE * 2) + ldSeg * 16);
            const __nv_bfloat16* gb = Bw + (size_t)(nBase + row) * KB + ch * 64 + ldSeg * 8;
            asm volatile("cp.async.cg.shared.global [%0], [%1], 16;" :: "r"(sbb), "l"(gb));
        }
        asm volatile("cp.async.commit_group;" ::: "memory");
    }

    for (int ch = 0; ch < 12; ch++) {
        int b = ch & 1;
        if (ch + 1 < 12) {
            int nb = (ch + 1) & 1;
#pragma unroll
            for (int i = 0; i < 4; i++) {
                int row = ldRow + i * 32;
                uint32_t sa = sA[nb] + (uint32_t)(row * (SSTRIDE * 2) + ldSeg * 16);
                const __nv_bfloat16* ga = A + (size_t)(mBase + row) * KB + (ch + 1) * 64 + ldSeg * 8;
                asm volatile("cp.async.cg.shared.global [%0], [%1], 16;" :: "r"(sa), "l"(ga));
                uint32_t sbb = sB[nb] + (uint32_t)(row * (SSTRIDE * 2) + ldSeg * 16);
                const __nv_bfloat16* gb = Bw + (size_t)(nBase + row) * KB + (ch + 1) * 64 + ldSeg * 8;
                asm volatile("cp.async.cg.shared.global [%0], [%1], 16;" :: "r"(sbb), "l"(gb));
            }
            asm volatile("cp.async.commit_group;" ::: "memory");
            asm volatile("cp.async.wait_group 1;" ::: "memory");
        } else {
            asm volatile("cp.async.wait_group 0;" ::: "memory");
        }
        __syncthreads();

#pragma unroll
        for (int ks = 0; ks < 4; ks++) {
            uint32_t a[4][4], bb[4][2];
#pragma unroll
            for (int mt = 0; mt < 4; mt++) {
                uint32_t addr = sA[b] + aAddr[mt] + ks * 32;
                asm volatile("ldmatrix.sync.aligned.m8n8.x4.shared.b16 {%0,%1,%2,%3}, [%4];"
                             : "=r"(a[mt][0]), "=r"(a[mt][1]), "=r"(a[mt][2]), "=r"(a[mt][3])
                             : "r"(addr));
            }
#pragma unroll
            for (int p = 0; p < 2; p++) {
                uint32_t addr = sB[b] + bAddr[p] + ks * 32;
                asm volatile("ldmatrix.sync.aligned.m8n8.x4.shared.b16 {%0,%1,%2,%3}, [%4];"
                             : "=r"(bb[2 * p][0]), "=r"(bb[2 * p][1]),
                               "=r"(bb[2 * p + 1][0]), "=r"(bb[2 * p + 1][1])
                             : "r"(addr));
            }
#pragma unroll
            for (int mt = 0; mt < 4; mt++)
#pragma unroll
                for (int nt = 0; nt < 4; nt++) {
                    asm volatile(
                        "mma.sync.aligned.m16n8k16.row.col.f32.bf16.bf16.f32 "
                        "{%0,%1,%2,%3}, {%4,%5,%6,%7}, {%8,%9}, {%0,%1,%2,%3};"
                        : "+f"(c[mt][nt][0]), "+f"(c[mt][nt][1]),
                          "+f"(c[mt][nt][2]), "+f"(c[mt][nt][3])
                        : "r"(a[mt][0]), "r"(a[mt][1]), "r"(a[mt][2]), "r"(a[mt][3]),
                          "r"(bb[nt][0]), "r"(bb[nt][1]));
                }
        }
        __syncthreads();
    }

#pragma unroll
    for (int mt = 0; mt < 4; mt++) {
        int r0 = mBase + wm * 64 + mt * 16 + (lane >> 2);
        int r1 = r0 + 8;
#pragma unroll
        for (int nt = 0; nt < 4; nt++) {
            int col = nBase + wn * 32 + nt * 8 + (lane & 3) * 2;
            float b0 = bias[col], b1 = bias[col + 1];
            if (r0 < M) {
                float2 v = make_float2(c[mt][nt][0] + b0, c[mt][nt][1] + b1);
                *reinterpret_cast<float2*>(C + (size_t)r0 * ldc + col) = v;
            }
            if (r1 < M) {
                float2 v = make_float2(c[mt][nt][2] + b0, c[mt][nt][3] + b1);
                *reinterpret_cast<float2*>(C + (size_t)r1 * ldc + col) = v;
            }
        }
    }
}

// ---------------- CSR build ----------------
__global__ void k_hist(const int* __restrict__ ei) {
    int t = blockIdx.x * blockDim.x + threadIdx.x;
    if (t < EE) atomicAdd(&g_deg[ei[EE + t]], 1);
}

__global__ void k_scan1() {
    __shared__ int sh[256];
    int b = blockIdx.x, tid = threadIdx.x;
    int i = b * 256 + tid;
    int v = (i < NN) ? g_deg[i] : 0;
    sh[tid] = v;
    __syncthreads();
    for (int o = 1; o < 256; o <<= 1) {
        int t = (tid >= o) ? sh[tid - o] : 0;
        __syncthreads();
        sh[tid] += t;
        __syncthreads();
    }
    if (i < NN) g_off[i] = sh[tid] - v;
    if (tid == 255) g_bsum[b] = sh[255];
}

__global__ void k_scan2() {
    __shared__ int sh[256];
    int tid = threadIdx.x;
    int v = (tid < 196) ? g_bsum[tid] : 0;
    sh[tid] = v;
    __syncthreads();
    for (int o = 1; o < 256; o <<= 1) {
        int t = (tid >= o) ? sh[tid - o] : 0;
        __syncthreads();
        sh[tid] += t;
        __syncthreads();
    }
    g_bsum[tid] = sh[tid] - v;
}

__global__ void k_scan3() {
    int i = blockIdx.x * 256 + threadIdx.x;
    if (i < NN) g_off[i] += g_bsum[blockIdx.x];
    if (i == 0) g_off[NN] = EE;
}

// bucket fill + per-edge geometry precompute (bucket order)
__global__ void k_bucket(const int* __restrict__ ei) {
    int t = blockIdx.x * blockDim.x + threadIdx.x;
    if (t < EE) {
        int s = ei[t];
        int d = ei[EE + t];
        int p = atomicAdd(&g_cur[d], 1);
        int pos = g_off[d] + p;
        g_bkt[pos] = t;
        float rx = g_nuv[2 * d]     - g_nuv[2 * s];
        float ry = g_nuv[2 * d + 1] - g_nuv[2 * s + 1];
        float dd = sqrtf(rx * rx + ry * ry);
        g_bgeo[pos] = make_float4(rx, ry, dd, __int_as_float(s));
    }
}

// ------- per-node attention: online softmax + aggregate + LN + SiLU + split --------
__global__ void k_agg(const float* __restrict__ att,
                      const float* __restrict__ We, const float* __restrict__ cb,
                      const float* __restrict__ ng, const float* __restrict__ nb) {
    int gw = (blockIdx.x * blockDim.x + threadIdx.x) >> 5;
    int lane = threadIdx.x & 31;
    if (gw >= NN) return;
    int n = gw;
    int h = lane >> 3;

    float attv[8], we0[8], we1[8], we2[8], xr[8], acc[8];
#pragma unroll
    for (int k = 0; k < 8; k++) {
        int j = lane * 8 + k;
        attv[k] = att[j];
        we0[k] = We[j * 3]; we1[k] = We[j * 3 + 1]; we2[k] = We[j * 3 + 2];
        acc[k] = 0.0f;
    }
    const float4* xrp = (const float4*)&g_xlri[(size_t)n * 768 + 256];
    {
        float4 a = xrp[lane * 2], b = xrp[lane * 2 + 1];
        xr[0] = a.x; xr[1] = a.y; xr[2] = a.z; xr[3] = a.w;
        xr[4] = b.x; xr[5] = b.y; xr[6] = b.z; xr[7] = b.w;
    }
    float m = -3.0e38f, s = 0.0f;
    int beg = g_off[n], end = g_off[n + 1];

    // software pipeline: prefetch next geo + x_l while computing current
    float4 geo, xa, xb;
    if (beg < end) {
        geo = g_bgeo[beg];
        int s0 = __float_as_int(geo.w);
        const float4* xp = (const float4*)&g_xlri[(size_t)s0 * 768];
        xa = xp[lane * 2]; xb = xp[lane * 2 + 1];
    }
    for (int i = beg; i < end; i++) {
        float4 geoC = geo;
        float xl[8] = {xa.x, xa.y, xa.z, xa.w, xb.x, xb.y, xb.z, xb.w};
        if (i + 1 < end) {
            geo = g_bgeo[i + 1];
            int s1 = __float_as_int(geo.w);
            const float4* xp = (const float4*)&g_xlri[(size_t)s1 * 768];
            xa = xp[lane * 2]; xb = xp[lane * 2 + 1];
        }
        float pp = 0.0f;
#pragma unroll
        for (int k = 0; k < 8; k++) {
            float z = xl[k] + xr[k] + (geoC.x * we0[k] + geoC.y * we1[k] + geoC.z * we2[k]);
            z = (z > 0.0f) ? z : 0.2f * z;
            pp += z * attv[k];
        }
        pp += __shfl_xor_sync(0xffffffffu, pp, 1);
        pp += __shfl_xor_sync(0xffffffffu, pp, 2);
        pp += __shfl_xor_sync(0xffffffffu, pp, 4);
        if ((lane & 7) == 0) g_logits[i * 4 + h] = pp;   // bucket-order sequential

        float mn = fmaxf(m, pp);
        float sc = __expf(m - mn);
        float p = __expf(pp - mn);
        s = s * sc + p;
        m = mn;
#pragma unroll
        for (int k = 0; k < 8; k++) acc[k] = acc[k] * sc + p * xl[k];
    }

    if ((lane & 7) == 0) { g_m[n * 4 + h] = m; g_s[n * 4 + h] = s; }

    float inv = (end > beg) ? (1.0f / s) : 0.0f;
    float o[8];
#pragma unroll
    for (int k = 0; k < 8; k++) o[k] = acc[k] * inv + cb[lane * 8 + k];

    float ps = 0.0f;
#pragma unroll
    for (int k = 0; k < 8; k++) ps += o[k];
    float mean = wsum(ps) * (1.0f / 256.0f);
    float pv = 0.0f;
#pragma unroll
    for (int k = 0; k < 8; k++) { float d = o[k] - mean; pv += d * d; }
    float var = wsum(pv) * (1.0f / 256.0f);
    float r = rsqrtf(var + 1e-5f);

    const float4* ip = (const float4*)&g_xlri[(size_t)n * 768 + 512];
    float4 ia = ip[lane * 2], ib = ip[lane * 2 + 1];
    float idv[8] = {ia.x, ia.y, ia.z, ia.w, ib.x, ib.y, ib.z, ib.w};
#pragma unroll
    for (int k = 0; k < 8; k++) {
        int j = lane * 8 + k;
        float y = (o[k] - mean) * r * ng[j] + nb[j] + idv[k];
        y = y / (1.0f + __expf(-y));
        write3(n, j, y);
    }
}

// ------- node-centric alpha + edge_attr output (no random gathers) -------
__global__ void k_alpha2(float* __restrict__ outA, float* __restrict__ outE) {
    int gw = (blockIdx.x * blockDim.x + threadIdx.x) >> 5;
    int lane = threadIdx.x & 31;
    if (gw >= NN) return;
    int n = gw;
    int beg = g_off[n], end = g_off[n + 1];
    int deg = end - beg;

    float mv[4], sv[4];
#pragma unroll
    for (int h = 0; h < 4; h++) {
        mv[h] = g_m[n * 4 + h];
        sv[h] = 1.0f / (g_s[n * 4 + h] + 1e-16f);
    }

    for (int j = lane; j < deg * 4; j += 32) {
        int pos = beg + (j >> 2);
        int h = j & 3;
        int e = g_bkt[pos];
        float a = __expf(g_logits[pos * 4 + h] - mv[h]) * sv[h];
        outA[(size_t)e * 4 + h] = a;
    }
    for (int j = lane; j < deg; j += 32) {
        int pos = beg + j;
        int e = g_bkt[pos];
        float4 g = g_bgeo[pos];
        outE[(size_t)e * 3]     = g.x;
        outE[(size_t)e * 3 + 1] = g.y;
        outE[(size_t)e * 3 + 2] = g.z;
    }
}

// ---------------- host launcher ----------------
extern "C" void kernel_launch(void* const* d_in, const int* in_sizes, int n_in,
                              void* d_out, int out_size) {
    const float* x      = (const float*)d_in[0];
    const float* kpts   = (const float*)d_in[1];
    const float* pts3d  = (const float*)d_in[2];
    const float* pe_w1  = (const float*)d_in[3];
    const float* pe_b1  = (const float*)d_in[4];
    const float* pe_g1  = (const float*)d_in[5];
    const float* pe_bn1 = (const float*)d_in[6];
    const float* pe_w2  = (const float*)d_in[7];
    const float* pe_b2  = (const float*)d_in[8];
    const float* pe_g2  = (const float*)d_in[9];
    const float* pe_bn2 = (const float*)d_in[10];
    const float* lin_l_w = (const float*)d_in[11];
    const float* lin_l_b = (const float*)d_in[12];
    const float* lin_r_w = (const float*)d_in[13];
    const float* lin_r_b = (const float*)d_in[14];
    const float* lin_edge_w = (const float*)d_in[15];
    const float* att    = (const float*)d_in[16];
    const float* conv_b = (const float*)d_in[17];
    const float* norm_g = (const float*)d_in[18];
    const float* norm_b = (const float*)d_in[19];
    const float* res_w  = (const float*)d_in[20];
    const float* res_b  = (const float*)d_in[21];
    const float* proj_w = (const float*)d_in[22];
    const float* proj_b = (const float*)d_in[23];
    const int*   ei     = (const int*)d_in[24];
    float* out = (float*)d_out;

    cudaFuncSetAttribute(k_mgemm, cudaFuncAttributeMaxDynamicSharedMemorySize, 4 * ABYTES);

    __nv_bfloat16* dA;  cudaGetSymbolAddress((void**)&dA,  g_Abig);
    __nv_bfloat16* dW;  cudaGetSymbolAddress((void**)&dW,  g_Wbig);
    __nv_bfloat16* dW2; cudaGetSymbolAddress((void**)&dW2, g_W2big);
    float* dB;    cudaGetSymbolAddress((void**)&dB,   g_B);
    float* dXLRI; cudaGetSymbolAddress((void**)&dXLRI, g_xlri);

    k_init<<<(NN + 255) / 256, 256>>>();
    k_node<<<(NN + 7) / 8, 256>>>(x, kpts, pts3d, pe_w1, pe_b1, pe_g1, pe_bn1,
                                  pe_w2, pe_b2, pe_g2, pe_bn2);
    k_concat<<<768, 256>>>(lin_l_w, lin_r_w, res_w, lin_l_b, lin_r_b, res_b);
    k_splitW2<<<256, 256>>>(proj_w);

    // gemm1: x_l | x_r | identity
    k_mgemm<<<dim3(6, 391), 256, 4 * ABYTES>>>(dA, dW, dB, dXLRI, NN, 768);

    k_hist<<<(EE + 255) / 256, 256>>>(ei);
    k_scan1<<<196, 256>>>();
    k_scan2<<<1, 256>>>();
    k_scan3<<<196, 256>>>();
    k_bucket<<<(EE + 255) / 256, 256>>>(ei);

    k_agg<<<(NN + 7) / 8, 256>>>(att, lin_edge_w, conv_b, norm_g, norm_b);

    k_alpha2<<<(NN + 7) / 8, 256>>>(out + NN * 256, out + NN * 256 + EE * 4);

    // gemm2: final projection
    k_mgemm<<<dim3(2, 391), 256, 4 * ABYTES>>>(dA, dW2, proj_b, out, NN, 256);
}

// round 6
// speedup vs baseline: 1.6402x; 1.0266x over previous
#include <cuda_runtime.h>
#include <cuda_bf16.h>
#include <math.h>
#include <stdint.h>

#define NN 50000
#define EE 800000
#define XD 192
#define MPAD 50048
#define KB 768          // split-K: [hi | hi | lo] x 256

// ---------------- scratch ----------------
static __device__ __nv_bfloat16 g_Abig[(size_t)MPAD * KB];   // A' splits
static __device__ __nv_bfloat16 g_Wbig[768 * KB];            // W' gemm1 (ll|lr|res)
static __device__ __nv_bfloat16 g_W2big[256 * KB];           // W' gemm2 (proj)
static __device__ float g_B[768];
static __device__ float g_nuv[NN * 2];
static __device__ float g_xlri[(size_t)NN * 768];            // x_l | x_r | identity
static __device__ float g_logits[EE * 4];                    // bucket-ordered
static __device__ float4 g_bgeo[EE];                         // (rx, ry, dist, src-bits)
static __device__ int   g_deg[NN];
static __device__ int   g_cur[NN];
static __device__ int   g_off[NN + 1];
static __device__ int   g_bkt[EE];
static __device__ int   g_bsum[256];

__device__ __forceinline__ float wsum(float v) {
#pragma unroll
    for (int o = 16; o > 0; o >>= 1) v += __shfl_xor_sync(0xffffffffu, v, o);
    return v;
}

__device__ __forceinline__ void write3(int n, int j, float v) {
    __nv_bfloat16 h = __float2bfloat16(v);
    float r = v - __bfloat162float(h);
    __nv_bfloat16 l = __float2bfloat16(r);
    size_t base = (size_t)n * KB;
    g_Abig[base + j]       = h;
    g_Abig[base + 256 + j] = h;
    g_Abig[base + 512 + j] = l;
}

__device__ __forceinline__ uint32_t s2u(const void* p) {
    uint32_t a;
    asm("{ .reg .u64 t; cvta.to.shared.u64 t, %1; cvt.u32.u64 %0, t; }" : "=r"(a) : "l"(p));
    return a;
}

// ---------------- init ----------------
__global__ void k_init() {
    int t = blockIdx.x * blockDim.x + threadIdx.x;
    if (t < NN) { g_deg[t] = 0; g_cur[t] = 0; }
}

// ---------------- pos encoder + A' assembly (1 warp / node) ----------------
__global__ void k_node(const float* __restrict__ x, const float* __restrict__ kpts,
                       const float* __restrict__ pts3d,
                       const float* __restrict__ w1, const float* __restrict__ b1,
                       const float* __restrict__ g1, const float* __restrict__ bn1,
                       const float* __restrict__ w2, const float* __restrict__ b2,
                       const float* __restrict__ g2, const float* __restrict__ bn2) {
    int gw = (blockIdx.x * blockDim.x + threadIdx.x) >> 5;
    int lane = threadIdx.x & 31;
    int w = threadIdx.x >> 5;
    if (gw >= NN) return;
    int n = gw;

    float nu = kpts[n * 2]     * (1.0f / 1216.0f);
    float nv = kpts[n * 2 + 1] * (1.0f / 352.0f);
    float dep = pts3d[n * 3 + 2];
    dep = fminf(fmaxf(dep, 0.1f), 100.0f);

    float h = nu * w1[lane * 3] + nv * w1[lane * 3 + 1] + dep * w1[lane * 3 + 2] + b1[lane];
    float mu = wsum(h) * (1.0f / 32.0f);
    float d = h - mu;
    float var = wsum(d * d) * (1.0f / 32.0f);
    float y = d * rsqrtf(var + 1e-5f) * g1[lane] + bn1[lane];
    y = y / (1.0f + __expf(-y));

    __shared__ float sh[8][32];
    sh[w][lane] = y;
    __syncwarp();

    float o0 = b2[lane], o1 = b2[lane + 32];
#pragma unroll
    for (int j = 0; j < 32; j++) {
        float hv = sh[w][j];
        o0 += hv * w2[lane * 32 + j];
        o1 += hv * w2[(lane + 32) * 32 + j];
    }
    float mean = wsum(o0 + o1) * (1.0f / 64.0f);
    float d0 = o0 - mean, d1 = o1 - mean;
    float v2 = wsum(d0 * d0 + d1 * d1) * (1.0f / 64.0f);
    float r = rsqrtf(v2 + 1e-5f);
    float p0 = d0 * r * g2[lane] + bn2[lane];
    float p1 = d1 * r * g2[lane + 32] + bn2[lane + 32];

#pragma unroll
    for (int i = 0; i < 6; i++) write3(n, lane + i * 32, x[n * XD + lane + i * 32]);
    write3(n, 192 + lane, p0);
    write3(n, 224 + lane, p1);

    if (lane == 0) { g_nuv[2 * n] = nu; g_nuv[2 * n + 1] = nv; }
}

// ---------------- weight splits ----------------
__global__ void k_concat(const float* ll, const float* lr, const float* rw,
                         const float* lb, const float* rb, const float* resb) {
    int t = blockIdx.x * blockDim.x + threadIdx.x;
    if (t < 196608) {
        float v;
        if (t < 65536)       v = ll[t];
        else if (t < 131072) v = lr[t - 65536];
        else                 v = rw[t - 131072];
        int row = t >> 8, col = t & 255;
        __nv_bfloat16 h = __float2bfloat16(v);
        __nv_bfloat16 l = __float2bfloat16(v - __bfloat162float(h));
        g_Wbig[row * KB + col]       = h;
        g_Wbig[row * KB + 256 + col] = l;
        g_Wbig[row * KB + 512 + col] = h;
    }
    if (t < 256)       g_B[t] = lb[t];
    else if (t < 512)  g_B[t] = rb[t - 256];
    else if (t < 768)  g_B[t] = resb[t - 512];
}

__global__ void k_splitW2(const float* pw) {
    int t = blockIdx.x * blockDim.x + threadIdx.x;
    if (t < 65536) {
        float v = pw[t];
        int row = t >> 8, col = t & 255;
        __nv_bfloat16 h = __float2bfloat16(v);
        __nv_bfloat16 l = __float2bfloat16(v - __bfloat162float(h));
        g_W2big[row * KB + col]       = h;
        g_W2big[row * KB + 256 + col] = l;
        g_W2big[row * KB + 512 + col] = h;
    }
}

// -------- mma.sync bf16 GEMM: C[M,*] = A'[M,768] * W'[Ncols,768]^T + bias --------
#define SSTRIDE 72
#define ABYTES  18432
__global__ void __launch_bounds__(256, 2) k_mgemm(const __nv_bfloat16* __restrict__ A,
                                                  const __nv_bfloat16* __restrict__ Bw,
                                                  const float* __restrict__ bias,
                                                  float* __restrict__ C, int M, int ldc) {
    extern __shared__ __align__(16) char smem[];
    const int tid = threadIdx.x, wid = tid >> 5, lane = tid & 31;
    const int mBase = blockIdx.y * 128;
    const int nBase = blockIdx.x * 128;
    const uint32_t sb = s2u(smem);
    const uint32_t sA[2] = {sb, sb + ABYTES};
    const uint32_t sB[2] = {sb + 2 * ABYTES, sb + 3 * ABYTES};

    const int wm = wid & 1;
    const int wn = wid >> 1;
    const int grp = lane >> 3;
    const int l8 = lane & 7;
    const int ldRow = tid >> 3;
    const int ldSeg = tid & 7;

    float c[4][4][4];
#pragma unroll
    for (int mt = 0; mt < 4; mt++)
#pragma unroll
        for (int nt = 0; nt < 4; nt++)
#pragma unroll
            for (int q = 0; q < 4; q++) c[mt][nt][q] = 0.0f;

    uint32_t aAddr[4];
#pragma unroll
    for (int mt = 0; mt < 4; mt++) {
        int row = wm * 64 + mt * 16 + (grp & 1) * 8 + l8;
        aAddr[mt] = (uint32_t)(row * (SSTRIDE * 2) + (grp >> 1) * 16);
    }
    uint32_t bAddr[2];
#pragma unroll
    for (int p = 0; p < 2; p++) {
        int nrow = wn * 32 + (2 * p + (grp >> 1)) * 8 + l8;
        bAddr[p] = (uint32_t)(nrow * (SSTRIDE * 2) + (grp & 1) * 16);
    }

    {
        const int b = 0, ch = 0;
#pragma unroll
        for (int i = 0; i < 4; i++) {
            int row = ldRow + i * 32;
            uint32_t sa = sA[b] + (uint32_t)(row * (SSTRIDE * 2) + ldSeg * 16);
            const __nv_bfloat16* ga = A + (size_t)(mBase + row) * KB + ch * 64 + ldSeg * 8;
            asm volatile("cp.async.cg.shared.global [%0], [%1], 16;" :: "r"(sa), "l"(ga));
            uint32_t sbb = sB[b] + (uint32_t)(row * (SSTRIDE * 2) + ldSeg * 16);
            const __nv_bfloat16* gb = Bw + (size_t)(nBase + row) * KB + ch * 64 + ldSeg * 8;
            asm volatile("cp.async.cg.shared.global [%0], [%1], 16;" :: "r"(sbb), "l"(gb));
        }
        asm volatile("cp.async.commit_group;" ::: "memory");
    }

    for (int ch = 0; ch < 12; ch++) {
        int b = ch & 1;
        if (ch + 1 < 12) {
            int nb = (ch + 1) & 1;
#pragma unroll
            for (int i = 0; i < 4; i++) {
                int row = ldRow + i * 32;
                uint32_t sa = sA[nb] + (uint32_t)(row * (SSTRIDE * 2) + ldSeg * 16);
                const __nv_bfloat16* ga = A + (size_t)(mBase + row) * KB + (ch + 1) * 64 + ldSeg * 8;
                asm volatile("cp.async.cg.shared.global [%0], [%1], 16;" :: "r"(sa), "l"(ga));
                uint32_t sbb = sB[nb] + (uint32_t)(row * (SSTRIDE * 2) + ldSeg * 16);
                const __nv_bfloat16* gb = Bw + (size_t)(nBase + row) * KB + (ch + 1) * 64 + ldSeg * 8;
                asm volatile("cp.async.cg.shared.global [%0], [%1], 16;" :: "r"(sbb), "l"(gb));
            }
            asm volatile("cp.async.commit_group;" ::: "memory");
            asm volatile("cp.async.wait_group 1;" ::: "memory");
        } else {
            asm volatile("cp.async.wait_group 0;" ::: "memory");
        }
        __syncthreads();

#pragma unroll
        for (int ks = 0; ks < 4; ks++) {
            uint32_t a[4][4], bb[4][2];
#pragma unroll
            for (int mt = 0; mt < 4; mt++) {
                uint32_t addr = sA[b] + aAddr[mt] + ks * 32;
                asm volatile("ldmatrix.sync.aligned.m8n8.x4.shared.b16 {%0,%1,%2,%3}, [%4];"
                             : "=r"(a[mt][0]), "=r"(a[mt][1]), "=r"(a[mt][2]), "=r"(a[mt][3])
                             : "r"(addr));
            }
#pragma unroll
            for (int p = 0; p < 2; p++) {
                uint32_t addr = sB[b] + bAddr[p] + ks * 32;
                asm volatile("ldmatrix.sync.aligned.m8n8.x4.shared.b16 {%0,%1,%2,%3}, [%4];"
                             : "=r"(bb[2 * p][0]), "=r"(bb[2 * p][1]),
                               "=r"(bb[2 * p + 1][0]), "=r"(bb[2 * p + 1][1])
                             : "r"(addr));
            }
#pragma unroll
            for (int mt = 0; mt < 4; mt++)
#pragma unroll
                for (int nt = 0; nt < 4; nt++) {
                    asm volatile(
                        "mma.sync.aligned.m16n8k16.row.col.f32.bf16.bf16.f32 "
                        "{%0,%1,%2,%3}, {%4,%5,%6,%7}, {%8,%9}, {%0,%1,%2,%3};"
                        : "+f"(c[mt][nt][0]), "+f"(c[mt][nt][1]),
                          "+f"(c[mt][nt][2]), "+f"(c[mt][nt][3])
                        : "r"(a[mt][0]), "r"(a[mt][1]), "r"(a[mt][2]), "r"(a[mt][3]),
                          "r"(bb[nt][0]), "r"(bb[nt][1]));
                }
        }
        __syncthreads();
    }

#pragma unroll
    for (int mt = 0; mt < 4; mt++) {
        int r0 = mBase + wm * 64 + mt * 16 + (lane >> 2);
        int r1 = r0 + 8;
#pragma unroll
        for (int nt = 0; nt < 4; nt++) {
            int col = nBase + wn * 32 + nt * 8 + (lane & 3) * 2;
            float b0 = bias[col], b1 = bias[col + 1];
            if (r0 < M) {
                float2 v = make_float2(c[mt][nt][0] + b0, c[mt][nt][1] + b1);
                *reinterpret_cast<float2*>(C + (size_t)r0 * ldc + col) = v;
            }
            if (r1 < M) {
                float2 v = make_float2(c[mt][nt][2] + b0, c[mt][nt][3] + b1);
                *reinterpret_cast<float2*>(C + (size_t)r1 * ldc + col) = v;
            }
        }
    }
}

// ---------------- CSR build ----------------
__global__ void k_hist(const int* __restrict__ ei) {
    int t = blockIdx.x * blockDim.x + threadIdx.x;
    if (t < EE) atomicAdd(&g_deg[ei[EE + t]], 1);
}

__global__ void k_scan1() {
    __shared__ int sh[256];
    int b = blockIdx.x, tid = threadIdx.x;
    int i = b * 256 + tid;
    int v = (i < NN) ? g_deg[i] : 0;
    sh[tid] = v;
    __syncthreads();
    for (int o = 1; o < 256; o <<= 1) {
        int t = (tid >= o) ? sh[tid - o] : 0;
        __syncthreads();
        sh[tid] += t;
        __syncthreads();
    }
    if (i < NN) g_off[i] = sh[tid] - v;
    if (tid == 255) g_bsum[b] = sh[255];
}

__global__ void k_scan2() {
    __shared__ int sh[256];
    int tid = threadIdx.x;
    int v = (tid < 196) ? g_bsum[tid] : 0;
    sh[tid] = v;
    __syncthreads();
    for (int o = 1; o < 256; o <<= 1) {
        int t = (tid >= o) ? sh[tid - o] : 0;
        __syncthreads();
        sh[tid] += t;
        __syncthreads();
    }
    g_bsum[tid] = sh[tid] - v;
}

__global__ void k_scan3() {
    int i = blockIdx.x * 256 + threadIdx.x;
    if (i < NN) g_off[i] += g_bsum[blockIdx.x];
    if (i == 0) g_off[NN] = EE;
}

// bucket fill + geometry precompute + edge_attr output (sequential by edge id)
__global__ void k_bucket(const int* __restrict__ ei, float* __restrict__ outE) {
    int t = blockIdx.x * blockDim.x + threadIdx.x;
    if (t < EE) {
        int s = ei[t];
        int d = ei[EE + t];
        int p = atomicAdd(&g_cur[d], 1);
        int pos = g_off[d] + p;
        g_bkt[pos] = t;
        float rx = g_nuv[2 * d]     - g_nuv[2 * s];
        float ry = g_nuv[2 * d + 1] - g_nuv[2 * s + 1];
        float dd = sqrtf(rx * rx + ry * ry);
        g_bgeo[pos] = make_float4(rx, ry, dd, __int_as_float(s));
        outE[(size_t)t * 3]     = rx;
        outE[(size_t)t * 3 + 1] = ry;
        outE[(size_t)t * 3 + 2] = dd;
    }
}

// ------- per-node attention: online softmax + aggregate + alpha + LN + SiLU + split ----
__global__ void k_agg(const float* __restrict__ att,
                      const float* __restrict__ We, const float* __restrict__ cb,
                      const float* __restrict__ ng, const float* __restrict__ nb,
                      float* __restrict__ outA) {
    int gw = (blockIdx.x * blockDim.x + threadIdx.x) >> 5;
    int lane = threadIdx.x & 31;
    if (gw >= NN) return;
    int n = gw;
    int h = lane >> 3;

    float attv[8], we0[8], we1[8], we2[8], xr[8], acc[8];
#pragma unroll
    for (int k = 0; k < 8; k++) {
        int j = lane * 8 + k;
        attv[k] = att[j];
        we0[k] = We[j * 3]; we1[k] = We[j * 3 + 1]; we2[k] = We[j * 3 + 2];
        acc[k] = 0.0f;
    }
    const float4* xrp = (const float4*)&g_xlri[(size_t)n * 768 + 256];
    {
        float4 a = xrp[lane * 2], b = xrp[lane * 2 + 1];
        xr[0] = a.x; xr[1] = a.y; xr[2] = a.z; xr[3] = a.w;
        xr[4] = b.x; xr[5] = b.y; xr[6] = b.z; xr[7] = b.w;
    }
    float m = -3.0e38f, s = 0.0f;
    int beg = g_off[n], end = g_off[n + 1];

    // software pipeline: geo 2 ahead, xl 1 ahead
    float4 geo0 = make_float4(0.f, 0.f, 0.f, 0.f), geo1 = geo0, xa = geo0, xb = geo0;
    if (beg < end) {
        geo0 = g_bgeo[beg];
        int s0 = __float_as_int(geo0.w);
        const float4* xp = (const float4*)&g_xlri[(size_t)s0 * 768];
        xa = xp[lane * 2]; xb = xp[lane * 2 + 1];
        geo1 = geo0;
        if (beg + 1 < end) geo1 = g_bgeo[beg + 1];
    }
    for (int i = beg; i < end; i++) {
        float4 geoC = geo0;
        float xl[8] = {xa.x, xa.y, xa.z, xa.w, xb.x, xb.y, xb.z, xb.w};
        geo0 = geo1;
        if (i + 2 < end) geo1 = g_bgeo[i + 2];
        if (i + 1 < end) {
            int s1 = __float_as_int(geo0.w);
            const float4* xp = (const float4*)&g_xlri[(size_t)s1 * 768];
            xa = xp[lane * 2]; xb = xp[lane * 2 + 1];
        }
        float pp = 0.0f;
#pragma unroll
        for (int k = 0; k < 8; k++) {
            float z = xl[k] + xr[k] + (geoC.x * we0[k] + geoC.y * we1[k] + geoC.z * we2[k]);
            z = (z > 0.0f) ? z : 0.2f * z;
            pp += z * attv[k];
        }
        pp += __shfl_xor_sync(0xffffffffu, pp, 1);
        pp += __shfl_xor_sync(0xffffffffu, pp, 2);
        pp += __shfl_xor_sync(0xffffffffu, pp, 4);
        if ((lane & 7) == 0) g_logits[i * 4 + h] = pp;   // bucket-order sequential

        float mn = fmaxf(m, pp);
        float sc = __expf(m - mn);
        float p = __expf(pp - mn);
        s = s * sc + p;
        m = mn;
#pragma unroll
        for (int k = 0; k < 8; k++) acc[k] = acc[k] * sc + p * xl[k];
    }

    // ---- alpha tail: warp rereads its own logits (L1/L2-hot) ----
    __threadfence_block();
    __syncwarp();
    {
        // hoist per-head (m, inv_s) broadcasts OUT of the divergent loop
        float m0 = __shfl_sync(0xffffffffu, m, 0);
        float m1 = __shfl_sync(0xffffffffu, m, 8);
        float m2 = __shfl_sync(0xffffffffu, m, 16);
        float m3 = __shfl_sync(0xffffffffu, m, 24);
        float i0 = 1.0f / (__shfl_sync(0xffffffffu, s, 0)  + 1e-16f);
        float i1 = 1.0f / (__shfl_sync(0xffffffffu, s, 8)  + 1e-16f);
        float i2 = 1.0f / (__shfl_sync(0xffffffffu, s, 16) + 1e-16f);
        float i3 = 1.0f / (__shfl_sync(0xffffffffu, s, 24) + 1e-16f);
        int deg = end - beg;
        for (int j = lane; j < deg * 4; j += 32) {
            int pos = beg + (j >> 2);
            int hh = j & 3;
            float mj = (hh == 0) ? m0 : (hh == 1) ? m1 : (hh == 2) ? m2 : m3;
            float ij = (hh == 0) ? i0 : (hh == 1) ? i1 : (hh == 2) ? i2 : i3;
            float a = __expf(g_logits[pos * 4 + hh] - mj) * ij;
            int e = g_bkt[pos];
            outA[(size_t)e * 4 + hh] = a;
        }
    }

    float inv = (end > beg) ? (1.0f / s) : 0.0f;
    float o[8];
#pragma unroll
    for (int k = 0; k < 8; k++) o[k] = acc[k] * inv + cb[lane * 8 + k];

    float ps = 0.0f;
#pragma unroll
    for (int k = 0; k < 8; k++) ps += o[k];
    float mean = wsum(ps) * (1.0f / 256.0f);
    float pv = 0.0f;
#pragma unroll
    for (int k = 0; k < 8; k++) { float d = o[k] - mean; pv += d * d; }
    float var = wsum(pv) * (1.0f / 256.0f);
    float r = rsqrtf(var + 1e-5f);

    const float4* ip = (const float4*)&g_xlri[(size_t)n * 768 + 512];
    float4 ia = ip[lane * 2], ib = ip[lane * 2 + 1];
    float idv[8] = {ia.x, ia.y, ia.z, ia.w, ib.x, ib.y, ib.z, ib.w};
#pragma unroll
    for (int k = 0; k < 8; k++) {
        int j = lane * 8 + k;
        float y = (o[k] - mean) * r * ng[j] + nb[j] + idv[k];
        y = y / (1.0f + __expf(-y));
        write3(n, j, y);
    }
}

// ---------------- host launcher ----------------
extern "C" void kernel_launch(void* const* d_in, const int* in_sizes, int n_in,
                              void* d_out, int out_size) {
    const float* x      = (const float*)d_in[0];
    const float* kpts   = (const float*)d_in[1];
    const float* pts3d  = (const float*)d_in[2];
    const float* pe_w1  = (const float*)d_in[3];
    const float* pe_b1  = (const float*)d_in[4];
    const float* pe_g1  = (const float*)d_in[5];
    const float* pe_bn1 = (const float*)d_in[6];
    const float* pe_w2  = (const float*)d_in[7];
    const float* pe_b2  = (const float*)d_in[8];
    const float* pe_g2  = (const float*)d_in[9];
    const float* pe_bn2 = (const float*)d_in[10];
    const float* lin_l_w = (const float*)d_in[11];
    const float* lin_l_b = (const float*)d_in[12];
    const float* lin_r_w = (const float*)d_in[13];
    const float* lin_r_b = (const float*)d_in[14];
    const float* lin_edge_w = (const float*)d_in[15];
    const float* att    = (const float*)d_in[16];
    const float* conv_b = (const float*)d_in[17];
    const float* norm_g = (const float*)d_in[18];
    const float* norm_b = (const float*)d_in[19];
    const float* res_w  = (const float*)d_in[20];
    const float* res_b  = (const float*)d_in[21];
    const float* proj_w = (const float*)d_in[22];
    const float* proj_b = (const float*)d_in[23];
    const int*   ei     = (const int*)d_in[24];
    float* out = (float*)d_out;

    cudaFuncSetAttribute(k_mgemm, cudaFuncAttributeMaxDynamicSharedMemorySize, 4 * ABYTES);

    __nv_bfloat16* dA;  cudaGetSymbolAddress((void**)&dA,  g_Abig);
    __nv_bfloat16* dW;  cudaGetSymbolAddress((void**)&dW,  g_Wbig);
    __nv_bfloat16* dW2; cudaGetSymbolAddress((void**)&dW2, g_W2big);
    float* dB;    cudaGetSymbolAddress((void**)&dB,   g_B);
    float* dXLRI; cudaGetSymbolAddress((void**)&dXLRI, g_xlri);

    k_init<<<(NN + 255) / 256, 256>>>();
    k_node<<<(NN + 7) / 8, 256>>>(x, kpts, pts3d, pe_w1, pe_b1, pe_g1, pe_bn1,
                                  pe_w2, pe_b2, pe_g2, pe_bn2);
    k_concat<<<768, 256>>>(lin_l_w, lin_r_w, res_w, lin_l_b, lin_r_b, res_b);
    k_splitW2<<<256, 256>>>(proj_w);

    // gemm1: x_l | x_r | identity
    k_mgemm<<<dim3(6, 391), 256, 4 * ABYTES>>>(dA, dW, dB, dXLRI, NN, 768);

    k_hist<<<(EE + 255) / 256, 256>>>(ei);
    k_scan1<<<196, 256>>>();
    k_scan2<<<1, 256>>>();
    k_scan3<<<196, 256>>>();
    k_bucket<<<(EE + 255) / 256, 256>>>(ei, out + NN * 256 + EE * 4);

    k_agg<<<(NN + 7) / 8, 256>>>(att, lin_edge_w, conv_b, norm_g, norm_b,
                                 out + NN * 256);

    // gemm2: final projection
    k_mgemm<<<dim3(2, 391), 256, 4 * ABYTES>>>(dA, dW2, proj_b, out, NN, 256);
}

// round 7
// speedup vs baseline: 1.6427x; 1.0015x over previous
#include <cuda_runtime.h>
#include <cuda_bf16.h>
#include <math.h>
#include <stdint.h>

#define NN 50000
#define EE 800000
#define XD 192
#define MPAD 50048
#define KB 768          // split-K: [hi | hi | lo] x 256

// ---------------- scratch ----------------
static __device__ __nv_bfloat16 g_Abig[(size_t)MPAD * KB];   // A' splits
static __device__ __nv_bfloat16 g_Wbig[768 * KB];            // W' gemm1 (ll|lr|res)
static __device__ __nv_bfloat16 g_W2big[256 * KB];           // W' gemm2 (proj)
static __device__ float g_B[768];
static __device__ float g_nuv[NN * 2];
static __device__ float g_xlri[(size_t)NN * 768];            // x_l | x_r | identity
static __device__ float g_logits[EE * 4];                    // bucket-ordered
static __device__ float4 g_bgeo[EE];                         // (rx, ry, dist, src-bits)
static __device__ int   g_deg[NN];
static __device__ int   g_cur[NN];
static __device__ int   g_off[NN + 1];
static __device__ int   g_bkt[EE];
static __device__ int   g_bsum[256];

__device__ __forceinline__ float wsum(float v) {
#pragma unroll
    for (int o = 16; o > 0; o >>= 1) v += __shfl_xor_sync(0xffffffffu, v, o);
    return v;
}

__device__ __forceinline__ void write3(int n, int j, float v) {
    __nv_bfloat16 h = __float2bfloat16(v);
    float r = v - __bfloat162float(h);
    __nv_bfloat16 l = __float2bfloat16(r);
    size_t base = (size_t)n * KB;
    g_Abig[base + j]       = h;
    g_Abig[base + 256 + j] = h;
    g_Abig[base + 512 + j] = l;
}

__device__ __forceinline__ uint32_t s2u(const void* p) {
    uint32_t a;
    asm("{ .reg .u64 t; cvta.to.shared.u64 t, %1; cvt.u32.u64 %0, t; }" : "=r"(a) : "l"(p));
    return a;
}

// ---------------- init ----------------
__global__ void k_init() {
    int t = blockIdx.x * blockDim.x + threadIdx.x;
    if (t < NN) { g_deg[t] = 0; g_cur[t] = 0; }
}

// ---------------- pos encoder + A' assembly (1 warp / node) ----------------
__global__ void k_node(const float* __restrict__ x, const float* __restrict__ kpts,
                       const float* __restrict__ pts3d,
                       const float* __restrict__ w1, const float* __restrict__ b1,
                       const float* __restrict__ g1, const float* __restrict__ bn1,
                       const float* __restrict__ w2, const float* __restrict__ b2,
                       const float* __restrict__ g2, const float* __restrict__ bn2) {
    int gw = (blockIdx.x * blockDim.x + threadIdx.x) >> 5;
    int lane = threadIdx.x & 31;
    int w = threadIdx.x >> 5;
    if (gw >= NN) return;
    int n = gw;

    float nu = kpts[n * 2]     * (1.0f / 1216.0f);
    float nv = kpts[n * 2 + 1] * (1.0f / 352.0f);
    float dep = pts3d[n * 3 + 2];
    dep = fminf(fmaxf(dep, 0.1f), 100.0f);

    float h = nu * w1[lane * 3] + nv * w1[lane * 3 + 1] + dep * w1[lane * 3 + 2] + b1[lane];
    float mu = wsum(h) * (1.0f / 32.0f);
    float d = h - mu;
    float var = wsum(d * d) * (1.0f / 32.0f);
    float y = d * rsqrtf(var + 1e-5f) * g1[lane] + bn1[lane];
    y = y / (1.0f + __expf(-y));

    __shared__ float sh[8][32];
    sh[w][lane] = y;
    __syncwarp();

    float o0 = b2[lane], o1 = b2[lane + 32];
#pragma unroll
    for (int j = 0; j < 32; j++) {
        float hv = sh[w][j];
        o0 += hv * w2[lane * 32 + j];
        o1 += hv * w2[(lane + 32) * 32 + j];
    }
    float mean = wsum(o0 + o1) * (1.0f / 64.0f);
    float d0 = o0 - mean, d1 = o1 - mean;
    float v2 = wsum(d0 * d0 + d1 * d1) * (1.0f / 64.0f);
    float r = rsqrtf(v2 + 1e-5f);
    float p0 = d0 * r * g2[lane] + bn2[lane];
    float p1 = d1 * r * g2[lane + 32] + bn2[lane + 32];

#pragma unroll
    for (int i = 0; i < 6; i++) write3(n, lane + i * 32, x[n * XD + lane + i * 32]);
    write3(n, 192 + lane, p0);
    write3(n, 224 + lane, p1);

    if (lane == 0) { g_nuv[2 * n] = nu; g_nuv[2 * n + 1] = nv; }
}

// ---------------- weight splits ----------------
__global__ void k_concat(const float* ll, const float* lr, const float* rw,
                         const float* lb, const float* rb, const float* resb) {
    int t = blockIdx.x * blockDim.x + threadIdx.x;
    if (t < 196608) {
        float v;
        if (t < 65536)       v = ll[t];
        else if (t < 131072) v = lr[t - 65536];
        else                 v = rw[t - 131072];
        int row = t >> 8, col = t & 255;
        __nv_bfloat16 h = __float2bfloat16(v);
        __nv_bfloat16 l = __float2bfloat16(v - __bfloat162float(h));
        g_Wbig[row * KB + col]       = h;
        g_Wbig[row * KB + 256 + col] = l;
        g_Wbig[row * KB + 512 + col] = h;
    }
    if (t < 256)       g_B[t] = lb[t];
    else if (t < 512)  g_B[t] = rb[t - 256];
    else if (t < 768)  g_B[t] = resb[t - 512];
}

__global__ void k_splitW2(const float* pw) {
    int t = blockIdx.x * blockDim.x + threadIdx.x;
    if (t < 65536) {
        float v = pw[t];
        int row = t >> 8, col = t & 255;
        __nv_bfloat16 h = __float2bfloat16(v);
        __nv_bfloat16 l = __float2bfloat16(v - __bfloat162float(h));
        g_W2big[row * KB + col]       = h;
        g_W2big[row * KB + 256 + col] = l;
        g_W2big[row * KB + 512 + col] = h;
    }
}

// -------- mma.sync bf16 GEMM: C[M,*] = A'[M,768] * W'[Ncols,768]^T + bias --------
#define SSTRIDE 72
#define ABYTES  18432
__global__ void __launch_bounds__(256, 2) k_mgemm(const __nv_bfloat16* __restrict__ A,
                                                  const __nv_bfloat16* __restrict__ Bw,
                                                  const float* __restrict__ bias,
                                                  float* __restrict__ C, int M, int ldc) {
    extern __shared__ __align__(16) char smem[];
    const int tid = threadIdx.x, wid = tid >> 5, lane = tid & 31;
    const int mBase = blockIdx.y * 128;
    const int nBase = blockIdx.x * 128;
    const uint32_t sb = s2u(smem);
    const uint32_t sA[2] = {sb, sb + ABYTES};
    const uint32_t sB[2] = {sb + 2 * ABYTES, sb + 3 * ABYTES};

    const int wm = wid & 1;
    const int wn = wid >> 1;
    const int grp = lane >> 3;
    const int l8 = lane & 7;
    const int ldRow = tid >> 3;
    const int ldSeg = tid & 7;

    float c[4][4][4];
#pragma unroll
    for (int mt = 0; mt < 4; mt++)
#pragma unroll
        for (int nt = 0; nt < 4; nt++)
#pragma unroll
            for (int q = 0; q < 4; q++) c[mt][nt][q] = 0.0f;

    uint32_t aAddr[4];
#pragma unroll
    for (int mt = 0; mt < 4; mt++) {
        int row = wm * 64 + mt * 16 + (grp & 1) * 8 + l8;
        aAddr[mt] = (uint32_t)(row * (SSTRIDE * 2) + (grp >> 1) * 16);
    }
    uint32_t bAddr[2];
#pragma unroll
    for (int p = 0; p < 2; p++) {
        int nrow = wn * 32 + (2 * p + (grp >> 1)) * 8 + l8;
        bAddr[p] = (uint32_t)(nrow * (SSTRIDE * 2) + (grp & 1) * 16);
    }

    {
        const int b = 0, ch = 0;
#pragma unroll
        for (int i = 0; i < 4; i++) {
            int row = ldRow + i * 32;
            uint32_t sa = sA[b] + (uint32_t)(row * (SSTRIDE * 2) + ldSeg * 16);
            const __nv_bfloat16* ga = A + (size_t)(mBase + row) * KB + ch * 64 + ldSeg * 8;
            asm volatile("cp.async.cg.shared.global [%0], [%1], 16;" :: "r"(sa), "l"(ga));
            uint32_t sbb = sB[b] + (uint32_t)(row * (SSTRIDE * 2) + ldSeg * 16);
            const __nv_bfloat16* gb = Bw + (size_t)(nBase + row) * KB + ch * 64 + ldSeg * 8;
            asm volatile("cp.async.cg.shared.global [%0], [%1], 16;" :: "r"(sbb), "l"(gb));
        }
        asm volatile("cp.async.commit_group;" ::: "memory");
    }

    for (int ch = 0; ch < 12; ch++) {
        int b = ch & 1;
        if (ch + 1 < 12) {
            int nb = (ch + 1) & 1;
#pragma unroll
            for (int i = 0; i < 4; i++) {
                int row = ldRow + i * 32;
                uint32_t sa = sA[nb] + (uint32_t)(row * (SSTRIDE * 2) + ldSeg * 16);
                const __nv_bfloat16* ga = A + (size_t)(mBase + row) * KB + (ch + 1) * 64 + ldSeg * 8;
                asm volatile("cp.async.cg.shared.global [%0], [%1], 16;" :: "r"(sa), "l"(ga));
                uint32_t sbb = sB[nb] + (uint32_t)(row * (SSTRIDE * 2) + ldSeg * 16);
                const __nv_bfloat16* gb = Bw + (size_t)(nBase + row) * KB + (ch + 1) * 64 + ldSeg * 8;
                asm volatile("cp.async.cg.shared.global [%0], [%1], 16;" :: "r"(sbb), "l"(gb));
            }
            asm volatile("cp.async.commit_group;" ::: "memory");
            asm volatile("cp.async.wait_group 1;" ::: "memory");
        } else {
            asm volatile("cp.async.wait_group 0;" ::: "memory");
        }
        __syncthreads();

#pragma unroll
        for (int ks = 0; ks < 4; ks++) {
            uint32_t a[4][4], bb[4][2];
#pragma unroll
            for (int mt = 0; mt < 4; mt++) {
                uint32_t addr = sA[b] + aAddr[mt] + ks * 32;
                asm volatile("ldmatrix.sync.aligned.m8n8.x4.shared.b16 {%0,%1,%2,%3}, [%4];"
                             : "=r"(a[mt][0]), "=r"(a[mt][1]), "=r"(a[mt][2]), "=r"(a[mt][3])
                             : "r"(addr));
            }
#pragma unroll
            for (int p = 0; p < 2; p++) {
                uint32_t addr = sB[b] + bAddr[p] + ks * 32;
                asm volatile("ldmatrix.sync.aligned.m8n8.x4.shared.b16 {%0,%1,%2,%3}, [%4];"
                             : "=r"(bb[2 * p][0]), "=r"(bb[2 * p][1]),
                               "=r"(bb[2 * p + 1][0]), "=r"(bb[2 * p + 1][1])
                             : "r"(addr));
            }
#pragma unroll
            for (int mt = 0; mt < 4; mt++)
#pragma unroll
                for (int nt = 0; nt < 4; nt++) {
                    asm volatile(
                        "mma.sync.aligned.m16n8k16.row.col.f32.bf16.bf16.f32 "
                        "{%0,%1,%2,%3}, {%4,%5,%6,%7}, {%8,%9}, {%0,%1,%2,%3};"
                        : "+f"(c[mt][nt][0]), "+f"(c[mt][nt][1]),
                          "+f"(c[mt][nt][2]), "+f"(c[mt][nt][3])
                        : "r"(a[mt][0]), "r"(a[mt][1]), "r"(a[mt][2]), "r"(a[mt][3]),
                          "r"(bb[nt][0]), "r"(bb[nt][1]));
                }
        }
        __syncthreads();
    }

#pragma unroll
    for (int mt = 0; mt < 4; mt++) {
        int r0 = mBase + wm * 64 + mt * 16 + (lane >> 2);
        int r1 = r0 + 8;
#pragma unroll
        for (int nt = 0; nt < 4; nt++) {
            int col = nBase + wn * 32 + nt * 8 + (lane & 3) * 2;
            float b0 = bias[col], b1 = bias[col + 1];
            if (r0 < M) {
                float2 v = make_float2(c[mt][nt][0] + b0, c[mt][nt][1] + b1);
                *reinterpret_cast<float2*>(C + (size_t)r0 * ldc + col) = v;
            }
            if (r1 < M) {
                float2 v = make_float2(c[mt][nt][2] + b0, c[mt][nt][3] + b1);
                *reinterpret_cast<float2*>(C + (size_t)r1 * ldc + col) = v;
            }
        }
    }
}

// ---------------- CSR build ----------------
__global__ void k_hist(const int* __restrict__ ei) {
    int t = blockIdx.x * blockDim.x + threadIdx.x;
    if (t < EE) atomicAdd(&g_deg[ei[EE + t]], 1);
}

__global__ void k_scan1() {
    __shared__ int sh[256];
    int b = blockIdx.x, tid = threadIdx.x;
    int i = b * 256 + tid;
    int v = (i < NN) ? g_deg[i] : 0;
    sh[tid] = v;
    __syncthreads();
    for (int o = 1; o < 256; o <<= 1) {
        int t = (tid >= o) ? sh[tid - o] : 0;
        __syncthreads();
        sh[tid] += t;
        __syncthreads();
    }
    if (i < NN) g_off[i] = sh[tid] - v;
    if (tid == 255) g_bsum[b] = sh[255];
}

__global__ void k_scan2() {
    __shared__ int sh[256];
    int tid = threadIdx.x;
    int v = (tid < 196) ? g_bsum[tid] : 0;
    sh[tid] = v;
    __syncthreads();
    for (int o = 1; o < 256; o <<= 1) {
        int t = (tid >= o) ? sh[tid - o] : 0;
        __syncthreads();
        sh[tid] += t;
        __syncthreads();
    }
    g_bsum[tid] = sh[tid] - v;
}

__global__ void k_scan3() {
    int i = blockIdx.x * 256 + threadIdx.x;
    if (i < NN) g_off[i] += g_bsum[blockIdx.x];
    if (i == 0) g_off[NN] = EE;
}

// bucket fill + geometry precompute + edge_attr output (sequential by edge id)
__global__ void k_bucket(const int* __restrict__ ei, float* __restrict__ outE) {
    int t = blockIdx.x * blockDim.x + threadIdx.x;
    if (t < EE) {
        int s = ei[t];
        int d = ei[EE + t];
        int p = atomicAdd(&g_cur[d], 1);
        int pos = g_off[d] + p;
        g_bkt[pos] = t;
        float rx = g_nuv[2 * d]     - g_nuv[2 * s];
        float ry = g_nuv[2 * d + 1] - g_nuv[2 * s + 1];
        float dd = sqrtf(rx * rx + ry * ry);
        g_bgeo[pos] = make_float4(rx, ry, dd, __int_as_float(s));
        outE[(size_t)t * 3]     = rx;
        outE[(size_t)t * 3 + 1] = ry;
        outE[(size_t)t * 3 + 2] = dd;
    }
}

// ------- per-node attention: online softmax + aggregate + alpha + LN + SiLU + split ----
__global__ void k_agg(const float* __restrict__ att,
                      const float* __restrict__ We, const float* __restrict__ cb,
                      const float* __restrict__ ng, const float* __restrict__ nb,
                      float* __restrict__ outA) {
    int gw = (blockIdx.x * blockDim.x + threadIdx.x) >> 5;
    int lane = threadIdx.x & 31;
    if (gw >= NN) return;
    int n = gw;
    int h = lane >> 3;

    float attv[8], we0[8], we1[8], we2[8], xr[8], acc[8];
#pragma unroll
    for (int k = 0; k < 8; k++) {
        int j = lane * 8 + k;
        attv[k] = att[j];
        we0[k] = We[j * 3]; we1[k] = We[j * 3 + 1]; we2[k] = We[j * 3 + 2];
        acc[k] = 0.0f;
    }
    const float4* xrp = (const float4*)&g_xlri[(size_t)n * 768 + 256];
    {
        float4 a = xrp[lane * 2], b = xrp[lane * 2 + 1];
        xr[0] = a.x; xr[1] = a.y; xr[2] = a.z; xr[3] = a.w;
        xr[4] = b.x; xr[5] = b.y; xr[6] = b.z; xr[7] = b.w;
    }
    float m = -3.0e38f, s = 0.0f;
    int beg = g_off[n], end = g_off[n + 1];

    // software pipeline: geo 2 ahead, xl 1 ahead
    float4 geo0 = make_float4(0.f, 0.f, 0.f, 0.f), geo1 = geo0, xa = geo0, xb = geo0;
    if (beg < end) {
        geo0 = g_bgeo[beg];
        int s0 = __float_as_int(geo0.w);
        const float4* xp = (const float4*)&g_xlri[(size_t)s0 * 768];
        xa = xp[lane * 2]; xb = xp[lane * 2 + 1];
        geo1 = geo0;
        if (beg + 1 < end) geo1 = g_bgeo[beg + 1];
    }
    for (int i = beg; i < end; i++) {
        float4 geoC = geo0;
        float xl[8] = {xa.x, xa.y, xa.z, xa.w, xb.x, xb.y, xb.z, xb.w};
        geo0 = geo1;
        if (i + 2 < end) geo1 = g_bgeo[i + 2];
        if (i + 1 < end) {
            int s1 = __float_as_int(geo0.w);
            const float4* xp = (const float4*)&g_xlri[(size_t)s1 * 768];
            xa = xp[lane * 2]; xb = xp[lane * 2 + 1];
        }
        float pp = 0.0f;
#pragma unroll
        for (int k = 0; k < 8; k++) {
            float z = xl[k] + xr[k] + (geoC.x * we0[k] + geoC.y * we1[k] + geoC.z * we2[k]);
            z = (z > 0.0f) ? z : 0.2f * z;
            pp += z * attv[k];
        }
        pp += __shfl_xor_sync(0xffffffffu, pp, 1);
        pp += __shfl_xor_sync(0xffffffffu, pp, 2);
        pp += __shfl_xor_sync(0xffffffffu, pp, 4);
        if ((lane & 7) == 0) g_logits[i * 4 + h] = pp;   // bucket-order sequential

        float mn = fmaxf(m, pp);
        float sc = __expf(m - mn);
        float p = __expf(pp - mn);
        s = s * sc + p;
        m = mn;
#pragma unroll
        for (int k = 0; k < 8; k++) acc[k] = acc[k] * sc + p * xl[k];
    }

    // ---- alpha tail: warp rereads its own logits (L1/L2-hot) ----
    __threadfence_block();
    __syncwarp();
    {
        // hoist per-head (m, inv_s) broadcasts OUT of the divergent loop
        float m0 = __shfl_sync(0xffffffffu, m, 0);
        float m1 = __shfl_sync(0xffffffffu, m, 8);
        float m2 = __shfl_sync(0xffffffffu, m, 16);
        float m3 = __shfl_sync(0xffffffffu, m, 24);
        float i0 = 1.0f / (__shfl_sync(0xffffffffu, s, 0)  + 1e-16f);
        float i1 = 1.0f / (__shfl_sync(0xffffffffu, s, 8)  + 1e-16f);
        float i2 = 1.0f / (__shfl_sync(0xffffffffu, s, 16) + 1e-16f);
        float i3 = 1.0f / (__shfl_sync(0xffffffffu, s, 24) + 1e-16f);
        int deg = end - beg;
        for (int j = lane; j < deg * 4; j += 32) {
            int pos = beg + (j >> 2);
            int hh = j & 3;
            float mj = (hh == 0) ? m0 : (hh == 1) ? m1 : (hh == 2) ? m2 : m3;
            float ij = (hh == 0) ? i0 : (hh == 1) ? i1 : (hh == 2) ? i2 : i3;
            float a = __expf(g_logits[pos * 4 + hh] - mj) * ij;
            int e = g_bkt[pos];
            outA[(size_t)e * 4 + hh] = a;
        }
    }

    float inv = (end > beg) ? (1.0f / s) : 0.0f;
    float o[8];
#pragma unroll
    for (int k = 0; k < 8; k++) o[k] = acc[k] * inv + cb[lane * 8 + k];

    float ps = 0.0f;
#pragma unroll
    for (int k = 0; k < 8; k++) ps += o[k];
    float mean = wsum(ps) * (1.0f / 256.0f);
    float pv = 0.0f;
#pragma unroll
    for (int k = 0; k < 8; k++) { float d = o[k] - mean; pv += d * d; }
    float var = wsum(pv) * (1.0f / 256.0f);
    float r = rsqrtf(var + 1e-5f);

    const float4* ip = (const float4*)&g_xlri[(size_t)n * 768 + 512];
    float4 ia = ip[lane * 2], ib = ip[lane * 2 + 1];
    float idv[8] = {ia.x, ia.y, ia.z, ia.w, ib.x, ib.y, ib.z, ib.w};
#pragma unroll
    for (int k = 0; k < 8; k++) {
        int j = lane * 8 + k;
        float y = (o[k] - mean) * r * ng[j] + nb[j] + idv[k];
        y = y / (1.0f + __expf(-y));
        write3(n, j, y);
    }
}

// ---------------- host launcher ----------------
extern "C" void kernel_launch(void* const* d_in, const int* in_sizes, int n_in,
                              void* d_out, int out_size) {
    const float* x      = (const float*)d_in[0];
    const float* kpts   = (const float*)d_in[1];
    const float* pts3d  = (const float*)d_in[2];
    const float* pe_w1  = (const float*)d_in[3];
    const float* pe_b1  = (const float*)d_in[4];
    const float* pe_g1  = (const float*)d_in[5];
    const float* pe_bn1 = (const float*)d_in[6];
    const float* pe_w2  = (const float*)d_in[7];
    const float* pe_b2  = (const float*)d_in[8];
    const float* pe_g2  = (const float*)d_in[9];
    const float* pe_bn2 = (const float*)d_in[10];
    const float* lin_l_w = (const float*)d_in[11];
    const float* lin_l_b = (const float*)d_in[12];
    const float* lin_r_w = (const float*)d_in[13];
    const float* lin_r_b = (const float*)d_in[14];
    const float* lin_edge_w = (const float*)d_in[15];
    const float* att    = (const float*)d_in[16];
    const float* conv_b = (const float*)d_in[17];
    const float* norm_g = (const float*)d_in[18];
    const float* norm_b = (const float*)d_in[19];
    const float* res_w  = (const float*)d_in[20];
    const float* res_b  = (const float*)d_in[21];
    const float* proj_w = (const float*)d_in[22];
    const float* proj_b = (const float*)d_in[23];
    const int*   ei     = (const int*)d_in[24];
    float* out = (float*)d_out;

    cudaFuncSetAttribute(k_mgemm, cudaFuncAttributeMaxDynamicSharedMemorySize, 4 * ABYTES);

    __nv_bfloat16* dA;  cudaGetSymbolAddress((void**)&dA,  g_Abig);
    __nv_bfloat16* dW;  cudaGetSymbolAddress((void**)&dW,  g_Wbig);
    __nv_bfloat16* dW2; cudaGetSymbolAddress((void**)&dW2, g_W2big);
    float* dB;    cudaGetSymbolAddress((void**)&dB,   g_B);
    float* dXLRI; cudaGetSymbolAddress((void**)&dXLRI, g_xlri);

    k_init<<<(NN + 255) / 256, 256>>>();
    k_node<<<(NN + 7) / 8, 256>>>(x, kpts, pts3d, pe_w1, pe_b1, pe_g1, pe_bn1,
                                  pe_w2, pe_b2, pe_g2, pe_bn2);
    k_concat<<<768, 256>>>(lin_l_w, lin_r_w, res_w, lin_l_b, lin_r_b, res_b);
    k_splitW2<<<256, 256>>>(proj_w);

    // gemm1: x_l | x_r | identity
    k_mgemm<<<dim3(6, 391), 256, 4 * ABYTES>>>(dA, dW, dB, dXLRI, NN, 768);

    k_hist<<<(EE + 255) / 256, 256>>>(ei);
    k_scan1<<<196, 256>>>();
    k_scan2<<<1, 256>>>();
    k_scan3<<<196, 256>>>();
    k_bucket<<<(EE + 255) / 256, 256>>>(ei, out + NN * 256 + EE * 4);

    k_agg<<<(NN + 7) / 8, 256>>>(att, lin_edge_w, conv_b, norm_g, norm_b,
                                 out + NN * 256);

    // gemm2: final projection
    k_mgemm<<<dim3(2, 391), 256, 4 * ABYTES>>>(dA, dW2, proj_b, out, NN, 256);
}